// round 2
// baseline (speedup 1.0000x reference)
#include <cuda_runtime.h>
#include <math.h>

#define BATCH 8
#define C 256
#define NPIX 4096
#define HIMG 64
#define WIMG 64
#define MRED 256      // 16*16 reduced tokens
#define HEADS 8
#define HD 32
#define ATTN_SCALE 0.17677669529663687f  // 32^-0.5
#define EPS 1e-5f

// ---------------- scratch (device globals; no allocation allowed) ------------
__device__ float g_xt[BATCH * C * NPIX];      // x transposed (b,c,n)
__device__ float g_q[BATCH * NPIX * C];       // q projection (b*n, c)
__device__ float g_kvred[BATCH * C * MRED];   // after sr conv + BN/GELU/BN
__device__ float g_kv2[BATCH * C * MRED];     // after local conv + residual
__device__ float g_kvp[BATCH * 2 * C * MRED]; // kv projection (b, 512, m)

// ---------------- 1) transpose x (b,n,c) -> (b,c,n) --------------------------
__global__ void transpose_kernel(const float* __restrict__ x) {
    __shared__ float tile[32][33];
    int b = blockIdx.z;
    int n0 = blockIdx.x * 32;
    int c0 = blockIdx.y * 32;
    #pragma unroll
    for (int r = threadIdx.y; r < 32; r += 8)
        tile[r][threadIdx.x] = x[((size_t)b * NPIX + n0 + r) * C + c0 + threadIdx.x];
    __syncthreads();
    #pragma unroll
    for (int r = threadIdx.y; r < 32; r += 8)
        g_xt[((size_t)b * C + c0 + r) * NPIX + n0 + threadIdx.x] = tile[threadIdx.x][r];
}

// ---------------- 2) q projection GEMM: Q = X * Wq^T + bq --------------------
// X: (B*N, C) row-major; Wq: (C_out, C_in) row-major. Out g_q (B*N, C).
__global__ __launch_bounds__(256) void gemm_q_kernel(
    const float* __restrict__ X, const float* __restrict__ Wq,
    const float* __restrict__ bq) {
    __shared__ float As[16][68];
    __shared__ float Bs[16][68];
    int bm = blockIdx.x * 64;
    int bn = blockIdx.y * 64;
    int tid = threadIdx.x;
    int tx = tid & 15, ty = tid >> 4;
    float acc[4][4];
    #pragma unroll
    for (int i = 0; i < 4; i++)
        #pragma unroll
        for (int j = 0; j < 4; j++) acc[i][j] = 0.f;

    for (int k0 = 0; k0 < C; k0 += 16) {
        #pragma unroll
        for (int i = tid; i < 64 * 16; i += 256) {
            int mm = i >> 4, kk = i & 15;
            As[kk][mm] = X[(size_t)(bm + mm) * C + k0 + kk];
            Bs[kk][mm] = Wq[(size_t)(bn + mm) * C + k0 + kk];  // B^T tile
        }
        __syncthreads();
        #pragma unroll
        for (int kk = 0; kk < 16; kk++) {
            float a[4], bb[4];
            #pragma unroll
            for (int i = 0; i < 4; i++) a[i] = As[kk][ty * 4 + i];
            #pragma unroll
            for (int j = 0; j < 4; j++) bb[j] = Bs[kk][tx * 4 + j];
            #pragma unroll
            for (int i = 0; i < 4; i++)
                #pragma unroll
                for (int j = 0; j < 4; j++) acc[i][j] += a[i] * bb[j];
        }
        __syncthreads();
    }
    #pragma unroll
    for (int i = 0; i < 4; i++) {
        int row = bm + ty * 4 + i;
        #pragma unroll
        for (int j = 0; j < 4; j++) {
            int col = bn + tx * 4 + j;
            g_q[(size_t)row * C + col] = acc[i][j] + bq[col];
        }
    }
}

// ---------------- 3) SR path: dwconv7 s4 p3 + BN1 + GELU + *w2 + BN2 ---------
__global__ __launch_bounds__(256) void srconv_kernel(
    const float* __restrict__ w7,
    const float* __restrict__ g1, const float* __restrict__ b1,
    const float* __restrict__ m1, const float* __restrict__ v1,
    const float* __restrict__ w2,
    const float* __restrict__ g2, const float* __restrict__ b2,
    const float* __restrict__ m2, const float* __restrict__ v2) {
    int c = blockIdx.x;
    int b = blockIdx.y;
    __shared__ float wsh[49];
    if (threadIdx.x < 49) wsh[threadIdx.x] = w7[c * 49 + threadIdx.x];
    __syncthreads();
    int oy = threadIdx.x >> 4;
    int ox = threadIdx.x & 15;
    const float* xp = g_xt + ((size_t)b * C + c) * NPIX;
    float s = 0.f;
    #pragma unroll
    for (int ky = 0; ky < 7; ky++) {
        int iy = oy * 4 - 3 + ky;
        if (iy < 0 || iy >= HIMG) continue;
        #pragma unroll
        for (int kx = 0; kx < 7; kx++) {
            int ix = ox * 4 - 3 + kx;
            if (ix < 0 || ix >= WIMG) continue;
            s += xp[iy * WIMG + ix] * wsh[ky * 7 + kx];
        }
    }
    float sc1 = g1[c] * rsqrtf(v1[c] + EPS);
    float val = s * sc1 + (b1[c] - m1[c] * sc1);
    val = 0.5f * val * (1.f + erff(val * 0.7071067811865476f));  // exact GELU
    val *= w2[c];
    float sc2 = g2[c] * rsqrtf(v2[c] + EPS);
    val = val * sc2 + (b2[c] - m2[c] * sc2);
    g_kvred[((size_t)b * C + c) * MRED + threadIdx.x] = val;
}

// ---------------- 4) local 3x3 dwconv + bias + residual ----------------------
__global__ __launch_bounds__(256) void localconv_kernel(
    const float* __restrict__ lw, const float* __restrict__ lb) {
    int c = blockIdx.x;
    int b = blockIdx.y;
    __shared__ float t[16][16];
    __shared__ float wl[9];
    if (threadIdx.x < 9) wl[threadIdx.x] = lw[c * 9 + threadIdx.x];
    int y = threadIdx.x >> 4;
    int xq = threadIdx.x & 15;
    const float* src = g_kvred + ((size_t)b * C + c) * MRED;
    t[y][xq] = src[threadIdx.x];
    __syncthreads();
    float s = lb[c];
    #pragma unroll
    for (int dy = -1; dy <= 1; dy++) {
        int yy = y + dy;
        if (yy < 0 || yy >= 16) continue;
        #pragma unroll
        for (int dx = -1; dx <= 1; dx++) {
            int xx = xq + dx;
            if (xx < 0 || xx >= 16) continue;
            s += t[yy][xx] * wl[(dy + 1) * 3 + (dx + 1)];
        }
    }
    g_kv2[((size_t)b * C + c) * MRED + threadIdx.x] = s + t[y][xq];
}

// ---------------- 5) kv projection: kvp[b] = Wkv * kv2[b] + bkv --------------
// Wkv (512, 256); kv2[b] (256, 256); out kvp (b, 512, 256)
__global__ __launch_bounds__(256) void gemm_kv_kernel(
    const float* __restrict__ Wkv, const float* __restrict__ bkv) {
    __shared__ float As[16][68];
    __shared__ float Bs[16][68];
    int bm = blockIdx.x * 64;
    int bn = blockIdx.y * 64;
    int b = blockIdx.z;
    int tid = threadIdx.x;
    int tx = tid & 15, ty = tid >> 4;
    const float* Bsrc = g_kv2 + (size_t)b * C * MRED;
    float acc[4][4];
    #pragma unroll
    for (int i = 0; i < 4; i++)
        #pragma unroll
        for (int j = 0; j < 4; j++) acc[i][j] = 0.f;

    for (int k0 = 0; k0 < C; k0 += 16) {
        #pragma unroll
        for (int i = tid; i < 64 * 16; i += 256) {
            int mm = i >> 4, kk = i & 15;
            As[kk][mm] = Wkv[(size_t)(bm + mm) * C + k0 + kk];
            int kk2 = i >> 6, nn = i & 63;
            Bs[kk2][nn] = Bsrc[(size_t)(k0 + kk2) * MRED + bn + nn];
        }
        __syncthreads();
        #pragma unroll
        for (int kk = 0; kk < 16; kk++) {
            float a[4], bb[4];
            #pragma unroll
            for (int i = 0; i < 4; i++) a[i] = As[kk][ty * 4 + i];
            #pragma unroll
            for (int j = 0; j < 4; j++) bb[j] = Bs[kk][tx * 4 + j];
            #pragma unroll
            for (int i = 0; i < 4; i++)
                #pragma unroll
                for (int j = 0; j < 4; j++) acc[i][j] += a[i] * bb[j];
        }
        __syncthreads();
    }
    #pragma unroll
    for (int i = 0; i < 4; i++) {
        int row = bm + ty * 4 + i;
        #pragma unroll
        for (int j = 0; j < 4; j++) {
            int col = bn + tx * 4 + j;
            g_kvp[(size_t)b * 2 * C * MRED + (size_t)row * MRED + col] =
                acc[i][j] + bkv[row];
        }
    }
}

// ---------------- 6) attention: online softmax, K/V in SMEM ------------------
// block = (query tile of 128, head, batch); smem: K[32][256] + V[32][256]
__global__ __launch_bounds__(128) void attn_kernel(float* __restrict__ out) {
    extern __shared__ float sm[];
    float* ks = sm;              // [HD][MRED], broadcast reads
    float* vs = sm + HD * MRED;  // [HD][MRED]
    int head = blockIdx.y;
    int b = blockIdx.z;
    const float* kb = g_kvp + ((size_t)b * 2 * C + head * HD) * MRED;
    const float* vb = g_kvp + ((size_t)b * 2 * C + C + head * HD) * MRED;
    for (int i = threadIdx.x; i < HD * MRED / 4; i += blockDim.x) {
        ((float4*)ks)[i] = ((const float4*)kb)[i];
        ((float4*)vs)[i] = ((const float4*)vb)[i];
    }
    __syncthreads();

    int pix = blockIdx.x * blockDim.x + threadIdx.x;
    const float* qp = g_q + ((size_t)(b * NPIX + pix)) * C + head * HD;
    float qr[HD];
    #pragma unroll
    for (int i = 0; i < HD / 4; i++) {
        float4 t = ((const float4*)qp)[i];
        qr[4 * i] = t.x; qr[4 * i + 1] = t.y;
        qr[4 * i + 2] = t.z; qr[4 * i + 3] = t.w;
    }
    float mx = -3e38f, sum = 0.f;
    float acc[HD];
    #pragma unroll
    for (int i = 0; i < HD; i++) acc[i] = 0.f;

    for (int m = 0; m < MRED; m++) {
        float s = 0.f;
        #pragma unroll
        for (int d = 0; d < HD; d++) s += qr[d] * ks[d * MRED + m];
        s *= ATTN_SCALE;
        if (s > mx) {  // lazy rescale: rare
            float corr = __expf(mx - s);
            sum *= corr;
            #pragma unroll
            for (int d = 0; d < HD; d++) acc[d] *= corr;
            mx = s;
        }
        float p = __expf(s - mx);
        sum += p;
        #pragma unroll
        for (int d = 0; d < HD; d++) acc[d] += p * vs[d * MRED + m];
    }
    float inv = 1.f / sum;
    float* op = out + ((size_t)(b * NPIX + pix)) * C + head * HD;
    #pragma unroll
    for (int i = 0; i < HD / 4; i++) {
        float4 t;
        t.x = acc[4 * i] * inv;     t.y = acc[4 * i + 1] * inv;
        t.z = acc[4 * i + 2] * inv; t.w = acc[4 * i + 3] * inv;
        ((float4*)op)[i] = t;
    }
}

// ---------------- launch ------------------------------------------------------
extern "C" void kernel_launch(void* const* d_in, const int* in_sizes, int n_in,
                              void* d_out, int out_size) {
    // input order: x, [h, w,] Wq, bq, Wkv, bkv, sr_w1, bn1_{g,b,m,v}, sr_w2,
    //              bn2_{g,b,m,v}, local_w, local_b
    int base = (n_in >= 19) ? 3 : 1;
    const float* x      = (const float*)d_in[0];
    const float* Wq     = (const float*)d_in[base + 0];
    const float* bq     = (const float*)d_in[base + 1];
    const float* Wkv    = (const float*)d_in[base + 2];
    const float* bkv    = (const float*)d_in[base + 3];
    const float* sr_w1  = (const float*)d_in[base + 4];
    const float* bn1g   = (const float*)d_in[base + 5];
    const float* bn1b   = (const float*)d_in[base + 6];
    const float* bn1m   = (const float*)d_in[base + 7];
    const float* bn1v   = (const float*)d_in[base + 8];
    const float* sr_w2  = (const float*)d_in[base + 9];
    const float* bn2g   = (const float*)d_in[base + 10];
    const float* bn2b   = (const float*)d_in[base + 11];
    const float* bn2m   = (const float*)d_in[base + 12];
    const float* bn2v   = (const float*)d_in[base + 13];
    const float* lw     = (const float*)d_in[base + 14];
    const float* lb     = (const float*)d_in[base + 15];
    float* out = (float*)d_out;

    cudaFuncSetAttribute(attn_kernel,
                         cudaFuncAttributeMaxDynamicSharedMemorySize, 65536);

    transpose_kernel<<<dim3(NPIX / 32, C / 32, BATCH), dim3(32, 8)>>>(x);
    gemm_q_kernel<<<dim3(BATCH * NPIX / 64, C / 64), 256>>>(x, Wq, bq);
    srconv_kernel<<<dim3(C, BATCH), 256>>>(sr_w1, bn1g, bn1b, bn1m, bn1v,
                                           sr_w2, bn2g, bn2b, bn2m, bn2v);
    localconv_kernel<<<dim3(C, BATCH), 256>>>(lw, lb);
    gemm_kv_kernel<<<dim3(2 * C / 64, MRED / 64, BATCH), 256>>>(Wkv, bkv);
    attn_kernel<<<dim3(NPIX / 128, HEADS, BATCH), 128, 65536>>>(out);
}

// round 3
// speedup vs baseline: 1.4931x; 1.4931x over previous
#include <cuda_runtime.h>
#include <math.h>
#include <string.h>

#define BATCH 8
#define C 256
#define NPIX 4096
#define HIMG 64
#define WIMG 64
#define MRED 256      // 16*16 reduced tokens
#define HEADS 8
#define HD 32
#define ATTN_SCALE 0.17677669529663687f  // 32^-0.5
#define EPS 1e-5f
#define KSTRIDE 34    // padded [m][d] row stride (8B-aligned, low-conflict)

// ---------------- scratch (device globals; no allocation allowed) ------------
__device__ float g_xt[BATCH * C * NPIX];      // x transposed (b,c,n)
__device__ float g_q[BATCH * NPIX * C];       // q projection (b*n, c)
__device__ float g_kvred[BATCH * C * MRED];   // after sr conv + BN/GELU/BN
__device__ float g_kv2[BATCH * C * MRED];     // after local conv + residual
__device__ float g_kvp[BATCH * 2 * C * MRED]; // kv projection (b, 512, m)

// ---------------- packed fp32x2 FMA (Blackwell FFMA2) -----------------------
__device__ __forceinline__ float2 ffma2(float2 a, float2 b, float2 c) {
    unsigned long long ua, ub, uc, ud;
    memcpy(&ua, &a, 8); memcpy(&ub, &b, 8); memcpy(&uc, &c, 8);
    asm("fma.rn.f32x2 %0, %1, %2, %3;" : "=l"(ud) : "l"(ua), "l"(ub), "l"(uc));
    float2 d; memcpy(&d, &ud, 8);
    return d;
}

// ---------------- 1) transpose x (b,n,c) -> (b,c,n) --------------------------
__global__ void transpose_kernel(const float* __restrict__ x) {
    __shared__ float tile[32][33];
    int b = blockIdx.z;
    int n0 = blockIdx.x * 32;
    int c0 = blockIdx.y * 32;
    #pragma unroll
    for (int r = threadIdx.y; r < 32; r += 8)
        tile[r][threadIdx.x] = x[((size_t)b * NPIX + n0 + r) * C + c0 + threadIdx.x];
    __syncthreads();
    #pragma unroll
    for (int r = threadIdx.y; r < 32; r += 8)
        g_xt[((size_t)b * C + c0 + r) * NPIX + n0 + threadIdx.x] = tile[threadIdx.x][r];
}

// ---------------- 2) q projection GEMM: Q = X * Wq^T + bq --------------------
// X: (B*N, C) row-major; Wq: (C_out, C_in) row-major. Out g_q (B*N, C).
__global__ __launch_bounds__(256) void gemm_q_kernel(
    const float* __restrict__ X, const float* __restrict__ Wq,
    const float* __restrict__ bq) {
    __shared__ float As[16][68];
    __shared__ float Bs[16][68];
    int bm = blockIdx.x * 64;
    int bn = blockIdx.y * 64;
    int tid = threadIdx.x;
    int tx = tid & 15, ty = tid >> 4;
    float2 acc[4][2];
    #pragma unroll
    for (int i = 0; i < 4; i++)
        #pragma unroll
        for (int j = 0; j < 2; j++) acc[i][j] = make_float2(0.f, 0.f);

    for (int k0 = 0; k0 < C; k0 += 16) {
        #pragma unroll
        for (int i = tid; i < 64 * 16; i += 256) {
            int mm = i >> 4, kk = i & 15;
            As[kk][mm] = X[(size_t)(bm + mm) * C + k0 + kk];
            Bs[kk][mm] = Wq[(size_t)(bn + mm) * C + k0 + kk];  // B^T tile
        }
        __syncthreads();
        #pragma unroll
        for (int kk = 0; kk < 16; kk++) {
            float2 b0 = *(const float2*)&Bs[kk][tx * 4];
            float2 b1 = *(const float2*)&Bs[kk][tx * 4 + 2];
            #pragma unroll
            for (int i = 0; i < 4; i++) {
                float a = As[kk][ty * 4 + i];
                float2 ap = make_float2(a, a);
                acc[i][0] = ffma2(ap, b0, acc[i][0]);
                acc[i][1] = ffma2(ap, b1, acc[i][1]);
            }
        }
        __syncthreads();
    }
    #pragma unroll
    for (int i = 0; i < 4; i++) {
        int row = bm + ty * 4 + i;
        #pragma unroll
        for (int j = 0; j < 2; j++) {
            int col = bn + tx * 4 + 2 * j;
            float2 v = acc[i][j];
            v.x += bq[col];
            v.y += bq[col + 1];
            *(float2*)&g_q[(size_t)row * C + col] = v;
        }
    }
}

// ---------------- 3) SR path: dwconv7 s4 p3 + BN1 + GELU + *w2 + BN2 ---------
__global__ __launch_bounds__(256) void srconv_kernel(
    const float* __restrict__ w7,
    const float* __restrict__ g1, const float* __restrict__ b1,
    const float* __restrict__ m1, const float* __restrict__ v1,
    const float* __restrict__ w2,
    const float* __restrict__ g2, const float* __restrict__ b2,
    const float* __restrict__ m2, const float* __restrict__ v2) {
    int c = blockIdx.x;
    int b = blockIdx.y;
    __shared__ float wsh[49];
    if (threadIdx.x < 49) wsh[threadIdx.x] = w7[c * 49 + threadIdx.x];
    __syncthreads();
    int oy = threadIdx.x >> 4;
    int ox = threadIdx.x & 15;
    const float* xp = g_xt + ((size_t)b * C + c) * NPIX;
    float s = 0.f;
    #pragma unroll
    for (int ky = 0; ky < 7; ky++) {
        int iy = oy * 4 - 3 + ky;
        if (iy < 0 || iy >= HIMG) continue;
        #pragma unroll
        for (int kx = 0; kx < 7; kx++) {
            int ix = ox * 4 - 3 + kx;
            if (ix < 0 || ix >= WIMG) continue;
            s += xp[iy * WIMG + ix] * wsh[ky * 7 + kx];
        }
    }
    float sc1 = g1[c] * rsqrtf(v1[c] + EPS);
    float val = s * sc1 + (b1[c] - m1[c] * sc1);
    val = 0.5f * val * (1.f + erff(val * 0.7071067811865476f));  // exact GELU
    val *= w2[c];
    float sc2 = g2[c] * rsqrtf(v2[c] + EPS);
    val = val * sc2 + (b2[c] - m2[c] * sc2);
    g_kvred[((size_t)b * C + c) * MRED + threadIdx.x] = val;
}

// ---------------- 4) local 3x3 dwconv + bias + residual ----------------------
__global__ __launch_bounds__(256) void localconv_kernel(
    const float* __restrict__ lw, const float* __restrict__ lb) {
    int c = blockIdx.x;
    int b = blockIdx.y;
    __shared__ float t[16][16];
    __shared__ float wl[9];
    if (threadIdx.x < 9) wl[threadIdx.x] = lw[c * 9 + threadIdx.x];
    int y = threadIdx.x >> 4;
    int xq = threadIdx.x & 15;
    const float* src = g_kvred + ((size_t)b * C + c) * MRED;
    t[y][xq] = src[threadIdx.x];
    __syncthreads();
    float s = lb[c];
    #pragma unroll
    for (int dy = -1; dy <= 1; dy++) {
        int yy = y + dy;
        if (yy < 0 || yy >= 16) continue;
        #pragma unroll
        for (int dx = -1; dx <= 1; dx++) {
            int xx = xq + dx;
            if (xx < 0 || xx >= 16) continue;
            s += t[yy][xx] * wl[(dy + 1) * 3 + (dx + 1)];
        }
    }
    g_kv2[((size_t)b * C + c) * MRED + threadIdx.x] = s + t[y][xq];
}

// ---------------- 5) kv projection: kvp[b] = Wkv * kv2[b] + bkv --------------
// Wkv (512, 256); kv2[b] (256, 256); out kvp (b, 512, 256)
__global__ __launch_bounds__(256) void gemm_kv_kernel(
    const float* __restrict__ Wkv, const float* __restrict__ bkv) {
    __shared__ float As[16][68];
    __shared__ float Bs[16][68];
    int bm = blockIdx.x * 64;
    int bn = blockIdx.y * 64;
    int b = blockIdx.z;
    int tid = threadIdx.x;
    int tx = tid & 15, ty = tid >> 4;
    const float* Bsrc = g_kv2 + (size_t)b * C * MRED;
    float2 acc[4][2];
    #pragma unroll
    for (int i = 0; i < 4; i++)
        #pragma unroll
        for (int j = 0; j < 2; j++) acc[i][j] = make_float2(0.f, 0.f);

    for (int k0 = 0; k0 < C; k0 += 16) {
        #pragma unroll
        for (int i = tid; i < 64 * 16; i += 256) {
            int mm = i >> 4, kk = i & 15;
            As[kk][mm] = Wkv[(size_t)(bm + mm) * C + k0 + kk];
            int kk2 = i >> 6, nn = i & 63;
            Bs[kk2][nn] = Bsrc[(size_t)(k0 + kk2) * MRED + bn + nn];
        }
        __syncthreads();
        #pragma unroll
        for (int kk = 0; kk < 16; kk++) {
            float2 b0 = *(const float2*)&Bs[kk][tx * 4];
            float2 b1 = *(const float2*)&Bs[kk][tx * 4 + 2];
            #pragma unroll
            for (int i = 0; i < 4; i++) {
                float a = As[kk][ty * 4 + i];
                float2 ap = make_float2(a, a);
                acc[i][0] = ffma2(ap, b0, acc[i][0]);
                acc[i][1] = ffma2(ap, b1, acc[i][1]);
            }
        }
        __syncthreads();
    }
    #pragma unroll
    for (int i = 0; i < 4; i++) {
        int row = bm + ty * 4 + i;
        float bias = bkv[row];
        #pragma unroll
        for (int j = 0; j < 2; j++) {
            int col = bn + tx * 4 + 2 * j;
            float2 v = acc[i][j];
            v.x += bias; v.y += bias;
            *(float2*)&g_kvp[(size_t)b * 2 * C * MRED + (size_t)row * MRED + col] = v;
        }
    }
}

// ---------------- 6) attention: online softmax, K/V in SMEM [m][d] ----------
// block = 128 threads x 2 queries = 256 queries; smem K,V: [MRED][KSTRIDE]
__global__ __launch_bounds__(128) void attn_kernel(float* __restrict__ out) {
    extern __shared__ float sm[];
    float* ks = sm;                    // [MRED][KSTRIDE]
    float* vs = sm + MRED * KSTRIDE;   // [MRED][KSTRIDE]
    int head = blockIdx.y;
    int b = blockIdx.z;
    const float* kb = g_kvp + ((size_t)b * 2 * C + head * HD) * MRED;
    const float* vb = kb + (size_t)C * MRED;
    // load + transpose [d][m] -> [m][d]
    for (int i = threadIdx.x; i < HD * MRED / 4; i += 128) {
        int d = i >> 6;
        int m4 = (i & 63) * 4;
        float4 kt = ((const float4*)kb)[i];
        float4 vt = ((const float4*)vb)[i];
        ks[(m4 + 0) * KSTRIDE + d] = kt.x;
        ks[(m4 + 1) * KSTRIDE + d] = kt.y;
        ks[(m4 + 2) * KSTRIDE + d] = kt.z;
        ks[(m4 + 3) * KSTRIDE + d] = kt.w;
        vs[(m4 + 0) * KSTRIDE + d] = vt.x;
        vs[(m4 + 1) * KSTRIDE + d] = vt.y;
        vs[(m4 + 2) * KSTRIDE + d] = vt.z;
        vs[(m4 + 3) * KSTRIDE + d] = vt.w;
    }
    __syncthreads();

    int q0 = blockIdx.x * 256 + threadIdx.x;   // query 0
    int q1 = q0 + 128;                          // query 1
    const float* qp0 = g_q + ((size_t)(b * NPIX + q0)) * C + head * HD;
    const float* qp1 = g_q + ((size_t)(b * NPIX + q1)) * C + head * HD;
    float2 qr0[HD / 2], qr1[HD / 2];
    #pragma unroll
    for (int i = 0; i < HD / 2; i++) {
        qr0[i] = ((const float2*)qp0)[i];
        qr1[i] = ((const float2*)qp1)[i];
    }
    float2 acc0[HD / 2], acc1[HD / 2];
    #pragma unroll
    for (int i = 0; i < HD / 2; i++) {
        acc0[i] = make_float2(0.f, 0.f);
        acc1[i] = make_float2(0.f, 0.f);
    }
    float mx0 = -3e38f, mx1 = -3e38f, sum0 = 0.f, sum1 = 0.f;

    for (int m = 0; m < MRED; m++) {
        const float2* krow = (const float2*)(ks + m * KSTRIDE);
        float2 s0v = make_float2(0.f, 0.f);
        float2 s1v = make_float2(0.f, 0.f);
        #pragma unroll
        for (int i = 0; i < HD / 2; i++) {
            float2 kd = krow[i];
            s0v = ffma2(qr0[i], kd, s0v);
            s1v = ffma2(qr1[i], kd, s1v);
        }
        float s0 = (s0v.x + s0v.y) * ATTN_SCALE;
        float s1 = (s1v.x + s1v.y) * ATTN_SCALE;
        if (s0 > mx0) {  // lazy rescale (rare)
            float corr = __expf(mx0 - s0);
            sum0 *= corr;
            #pragma unroll
            for (int i = 0; i < HD / 2; i++) {
                acc0[i].x *= corr; acc0[i].y *= corr;
            }
            mx0 = s0;
        }
        if (s1 > mx1) {
            float corr = __expf(mx1 - s1);
            sum1 *= corr;
            #pragma unroll
            for (int i = 0; i < HD / 2; i++) {
                acc1[i].x *= corr; acc1[i].y *= corr;
            }
            mx1 = s1;
        }
        float p0 = __expf(s0 - mx0);
        float p1 = __expf(s1 - mx1);
        sum0 += p0;
        sum1 += p1;
        float2 p0p = make_float2(p0, p0);
        float2 p1p = make_float2(p1, p1);
        const float2* vrow = (const float2*)(vs + m * KSTRIDE);
        #pragma unroll
        for (int i = 0; i < HD / 2; i++) {
            float2 vd = vrow[i];
            acc0[i] = ffma2(p0p, vd, acc0[i]);
            acc1[i] = ffma2(p1p, vd, acc1[i]);
        }
    }
    float inv0 = 1.f / sum0;
    float inv1 = 1.f / sum1;
    float* op0 = out + ((size_t)(b * NPIX + q0)) * C + head * HD;
    float* op1 = out + ((size_t)(b * NPIX + q1)) * C + head * HD;
    #pragma unroll
    for (int i = 0; i < HD / 2; i++) {
        float2 t0 = acc0[i], t1 = acc1[i];
        t0.x *= inv0; t0.y *= inv0;
        t1.x *= inv1; t1.y *= inv1;
        ((float2*)op0)[i] = t0;
        ((float2*)op1)[i] = t1;
    }
}

// ---------------- launch ------------------------------------------------------
extern "C" void kernel_launch(void* const* d_in, const int* in_sizes, int n_in,
                              void* d_out, int out_size) {
    int base = (n_in >= 19) ? 3 : 1;
    const float* x      = (const float*)d_in[0];
    const float* Wq     = (const float*)d_in[base + 0];
    const float* bq     = (const float*)d_in[base + 1];
    const float* Wkv    = (const float*)d_in[base + 2];
    const float* bkv    = (const float*)d_in[base + 3];
    const float* sr_w1  = (const float*)d_in[base + 4];
    const float* bn1g   = (const float*)d_in[base + 5];
    const float* bn1b   = (const float*)d_in[base + 6];
    const float* bn1m   = (const float*)d_in[base + 7];
    const float* bn1v   = (const float*)d_in[base + 8];
    const float* sr_w2  = (const float*)d_in[base + 9];
    const float* bn2g   = (const float*)d_in[base + 10];
    const float* bn2b   = (const float*)d_in[base + 11];
    const float* bn2m   = (const float*)d_in[base + 12];
    const float* bn2v   = (const float*)d_in[base + 13];
    const float* lw     = (const float*)d_in[base + 14];
    const float* lb     = (const float*)d_in[base + 15];
    float* out = (float*)d_out;

    const int attn_smem = 2 * MRED * KSTRIDE * sizeof(float);
    cudaFuncSetAttribute(attn_kernel,
                         cudaFuncAttributeMaxDynamicSharedMemorySize, attn_smem);

    transpose_kernel<<<dim3(NPIX / 32, C / 32, BATCH), dim3(32, 8)>>>(x);
    gemm_q_kernel<<<dim3(BATCH * NPIX / 64, C / 64), 256>>>(x, Wq, bq);
    srconv_kernel<<<dim3(C, BATCH), 256>>>(sr_w1, bn1g, bn1b, bn1m, bn1v,
                                           sr_w2, bn2g, bn2b, bn2m, bn2v);
    localconv_kernel<<<dim3(C, BATCH), 256>>>(lw, lb);
    gemm_kv_kernel<<<dim3(2 * C / 64, MRED / 64, BATCH), 256>>>(Wkv, bkv);
    attn_kernel<<<dim3(NPIX / 256, HEADS, BATCH), 128, attn_smem>>>(out);
}

// round 5
// speedup vs baseline: 2.4561x; 1.6449x over previous
#include <cuda_runtime.h>
#include <cuda_bf16.h>
#include <math.h>
#include <string.h>

#define BATCH 8
#define C 256
#define NPIX 4096
#define HIMG 64
#define WIMG 64
#define MRED 256
#define HEADS 8
#define HD 32
#define ATTN_SCALE 0.17677669529663687f
#define EPS 1e-5f

// ---------------- scratch ----------------------------------------------------
__device__ float g_q[BATCH * NPIX * C];       // (b*n, c)
__device__ float g_kvred[BATCH * MRED * C];   // (b, m, c)
__device__ float g_kv2[BATCH * MRED * C];     // (b, m, c)
__device__ float g_kvp[BATCH * MRED * 2 * C]; // (b, m, 512)

// ---------------- helpers ------------------------------------------------------
__device__ __forceinline__ float2 ffma2(float2 a, float2 b, float2 c) {
    unsigned long long ua, ub, uc, ud;
    memcpy(&ua, &a, 8); memcpy(&ub, &b, 8); memcpy(&uc, &c, 8);
    asm("fma.rn.f32x2 %0, %1, %2, %3;" : "=l"(ud) : "l"(ua), "l"(ub), "l"(uc));
    float2 d; memcpy(&d, &ud, 8);
    return d;
}

__device__ __forceinline__ unsigned smem_u32(const void* p) {
    unsigned a;
    asm("{ .reg .u64 t; cvta.to.shared.u64 t, %1; cvt.u32.u64 %0, t; }"
        : "=r"(a) : "l"(p));
    return a;
}

__device__ __forceinline__ void ldmx4(unsigned* r, unsigned addr) {
    asm volatile("ldmatrix.sync.aligned.m8n8.x4.shared.b16 {%0,%1,%2,%3}, [%4];"
                 : "=r"(r[0]), "=r"(r[1]), "=r"(r[2]), "=r"(r[3]) : "r"(addr));
}
__device__ __forceinline__ void ldmx2(unsigned& b0, unsigned& b1, unsigned addr) {
    asm volatile("ldmatrix.sync.aligned.m8n8.x2.shared.b16 {%0,%1}, [%2];"
                 : "=r"(b0), "=r"(b1) : "r"(addr));
}
__device__ __forceinline__ void mma_bf16(float* c, const unsigned* a,
                                         unsigned b0, unsigned b1) {
    asm volatile(
        "mma.sync.aligned.m16n8k16.row.col.f32.bf16.bf16.f32 "
        "{%0,%1,%2,%3}, {%4,%5,%6,%7}, {%8,%9}, {%0,%1,%2,%3};"
        : "+f"(c[0]), "+f"(c[1]), "+f"(c[2]), "+f"(c[3])
        : "r"(a[0]), "r"(a[1]), "r"(a[2]), "r"(a[3]), "r"(b0), "r"(b1));
}
__device__ __forceinline__ unsigned pack_bf16x2(float lo, float hi) {
    unsigned d;
    asm("cvt.rn.bf16x2.f32 %0, %1, %2;" : "=r"(d) : "f"(hi), "f"(lo));
    return d;
}

// ---------------- generic GEMM (FFMA2): Out = X·W^T + bias -------------------
__global__ __launch_bounds__(256) void gemm_xw_kernel(
    const float* __restrict__ X, const float* __restrict__ W,
    const float* __restrict__ bias, float* __restrict__ Out, int ncols) {
    __shared__ float As[16][68];
    __shared__ float Bs[16][68];
    int bm = blockIdx.x * 64;
    int bn = blockIdx.y * 64;
    int tid = threadIdx.x;
    int tx = tid & 15, ty = tid >> 4;
    float2 acc[4][2];
    #pragma unroll
    for (int i = 0; i < 4; i++)
        #pragma unroll
        for (int j = 0; j < 2; j++) acc[i][j] = make_float2(0.f, 0.f);

    for (int k0 = 0; k0 < C; k0 += 16) {
        #pragma unroll
        for (int i = tid; i < 64 * 16; i += 256) {
            int mm = i >> 4, kk = i & 15;
            As[kk][mm] = X[(size_t)(bm + mm) * C + k0 + kk];
            Bs[kk][mm] = W[(size_t)(bn + mm) * C + k0 + kk];
        }
        __syncthreads();
        #pragma unroll
        for (int kk = 0; kk < 16; kk++) {
            float2 b0 = *(const float2*)&Bs[kk][tx * 4];
            float2 b1 = *(const float2*)&Bs[kk][tx * 4 + 2];
            #pragma unroll
            for (int i = 0; i < 4; i++) {
                float a = As[kk][ty * 4 + i];
                float2 ap = make_float2(a, a);
                acc[i][0] = ffma2(ap, b0, acc[i][0]);
                acc[i][1] = ffma2(ap, b1, acc[i][1]);
            }
        }
        __syncthreads();
    }
    #pragma unroll
    for (int i = 0; i < 4; i++) {
        int row = bm + ty * 4 + i;
        #pragma unroll
        for (int j = 0; j < 2; j++) {
            int col = bn + tx * 4 + 2 * j;
            float2 v = acc[i][j];
            v.x += bias[col];
            v.y += bias[col + 1];
            *(float2*)&Out[(size_t)row * ncols + col] = v;
        }
    }
}

// ---------------- SR conv: reads x (b,n,c) directly, writes (b,m,c) ----------
__global__ __launch_bounds__(256) void srconv_kernel(
    const float* __restrict__ x, const float* __restrict__ w7,
    const float* __restrict__ g1, const float* __restrict__ b1,
    const float* __restrict__ m1, const float* __restrict__ v1,
    const float* __restrict__ w2,
    const float* __restrict__ g2, const float* __restrict__ b2,
    const float* __restrict__ m2, const float* __restrict__ v2) {
    int opix = blockIdx.x;
    int b = blockIdx.y;
    int c = threadIdx.x;
    int oy = opix >> 4, ox = opix & 15;
    const float* xb = x + (size_t)b * NPIX * C;
    float s = 0.f;
    #pragma unroll
    for (int ky = 0; ky < 7; ky++) {
        int iy = oy * 4 - 3 + ky;
        if (iy < 0 || iy >= HIMG) continue;
        #pragma unroll
        for (int kx = 0; kx < 7; kx++) {
            int ix = ox * 4 - 3 + kx;
            if (ix < 0 || ix >= WIMG) continue;
            s += xb[(size_t)(iy * WIMG + ix) * C + c] * w7[c * 49 + ky * 7 + kx];
        }
    }
    float sc1 = g1[c] * rsqrtf(v1[c] + EPS);
    float val = s * sc1 + (b1[c] - m1[c] * sc1);
    val = 0.5f * val * (1.f + erff(val * 0.7071067811865476f));
    val *= w2[c];
    float sc2 = g2[c] * rsqrtf(v2[c] + EPS);
    val = val * sc2 + (b2[c] - m2[c] * sc2);
    g_kvred[((size_t)b * MRED + opix) * C + c] = val;
}

// ---------------- local 3x3 dwconv + bias + residual, (b,m,c) layout ---------
__global__ __launch_bounds__(256) void localconv_kernel(
    const float* __restrict__ lw, const float* __restrict__ lb) {
    int opix = blockIdx.x;
    int b = blockIdx.y;
    int c = threadIdx.x;
    int y = opix >> 4, xq = opix & 15;
    const float* src = g_kvred + (size_t)b * MRED * C;
    float ctr = src[(size_t)opix * C + c];
    float s = lb[c] + ctr;
    #pragma unroll
    for (int dy = -1; dy <= 1; dy++) {
        int yy = y + dy;
        if (yy < 0 || yy >= 16) continue;
        #pragma unroll
        for (int dx = -1; dx <= 1; dx++) {
            int xx = xq + dx;
            if (xx < 0 || xx >= 16) continue;
            s += src[(size_t)(yy * 16 + xx) * C + c] * lw[c * 9 + (dy + 1) * 3 + (dx + 1)];
        }
    }
    g_kv2[((size_t)b * MRED + opix) * C + c] = s;
}

// ---------------- flash attention via mma.sync bf16 ---------------------------
// block = (q-tile 128, head, b), 256 threads (8 warps, warp owns 16 q rows)
#define QSTR 40    // K/Q smem row stride (bf16): 80 B, conflict-free ldmatrix
#define VSTR 264   // Vt smem row stride (bf16): 528 B, conflict-free ldmatrix
#define SM_QHI 0
#define SM_QLO (SM_QHI + 128 * QSTR)
#define SM_KHI (SM_QLO + 128 * QSTR)
#define SM_KLO (SM_KHI + 256 * QSTR)
#define SM_VT  (SM_KLO + 256 * QSTR)
#define ATTN_SMEM ((SM_VT + 32 * VSTR) * 2)

__global__ __launch_bounds__(256) void attn_kernel(float* __restrict__ out) {
    extern __shared__ __nv_bfloat16 sm[];
    __nv_bfloat16* qhi = sm + SM_QHI;
    __nv_bfloat16* qlo = sm + SM_QLO;
    __nv_bfloat16* khi = sm + SM_KHI;
    __nv_bfloat16* klo = sm + SM_KLO;
    __nv_bfloat16* vt  = sm + SM_VT;

    int tid = threadIdx.x, lane = tid & 31, w = tid >> 5;
    int qt = blockIdx.x, head = blockIdx.y, b = blockIdx.z;
    const float QSC = ATTN_SCALE * 1.4426950408889634f;  // scale * log2(e)

    // ---- stage Q (scaled, hi/lo split) ----
    for (int i = tid; i < 128 * 16; i += 256) {
        int n = i >> 4, d2 = (i & 15) * 2;
        float2 v = *(const float2*)(g_q + ((size_t)(b * NPIX + qt * 128 + n)) * C
                                    + head * HD + d2);
        float a0 = v.x * QSC, a1 = v.y * QSC;
        __nv_bfloat16 h0 = __float2bfloat16(a0);
        __nv_bfloat16 h1 = __float2bfloat16(a1);
        qhi[n * QSTR + d2] = h0;
        qhi[n * QSTR + d2 + 1] = h1;
        qlo[n * QSTR + d2] = __float2bfloat16(a0 - __bfloat162float(h0));
        qlo[n * QSTR + d2 + 1] = __float2bfloat16(a1 - __bfloat162float(h1));
    }
    // ---- stage K (hi/lo) and V transposed [d][key] ----
    for (int i = tid; i < 256 * 16; i += 256) {
        int m = i >> 4, d2 = (i & 15) * 2;
        const float* kr = g_kvp + ((size_t)(b * MRED + m)) * (2 * C) + head * HD;
        float2 kv = *(const float2*)(kr + d2);
        __nv_bfloat16 h0 = __float2bfloat16(kv.x);
        __nv_bfloat16 h1 = __float2bfloat16(kv.y);
        khi[m * QSTR + d2] = h0;
        khi[m * QSTR + d2 + 1] = h1;
        klo[m * QSTR + d2] = __float2bfloat16(kv.x - __bfloat162float(h0));
        klo[m * QSTR + d2 + 1] = __float2bfloat16(kv.y - __bfloat162float(h1));
        float2 vv = *(const float2*)(kr + C + d2);
        vt[d2 * VSTR + m] = __float2bfloat16(vv.x);
        vt[(d2 + 1) * VSTR + m] = __float2bfloat16(vv.y);
    }
    __syncthreads();

    // ---- Q A-fragments (2 k-tiles, hi+lo) ----
    int m0 = w * 16;
    unsigned qh[2][4], ql[2][4];
    #pragma unroll
    for (int kt = 0; kt < 2; kt++) {
        int row = m0 + (lane & 15);
        int col = kt * 16 + (lane >> 4) * 8;
        ldmx4(qh[kt], smem_u32(qhi + row * QSTR + col));
        ldmx4(ql[kt], smem_u32(qlo + row * QSTR + col));
    }

    float m_lo = -1e30f, m_hi = -1e30f, sum_lo = 0.f, sum_hi = 0.f;
    float o[4][4];
    #pragma unroll
    for (int i = 0; i < 4; i++)
        #pragma unroll
        for (int j = 0; j < 4; j++) o[i][j] = 0.f;

    #pragma unroll
    for (int kb = 0; kb < 4; kb++) {
        // ---- S = Q·K^T (3-term bf16 split) for 64 keys ----
        float s[8][4];
        #pragma unroll
        for (int j = 0; j < 8; j++)
            #pragma unroll
            for (int q = 0; q < 4; q++) s[j][q] = 0.f;
        #pragma unroll
        for (int kt = 0; kt < 2; kt++) {
            #pragma unroll
            for (int j = 0; j < 8; j++) {
                int row = kb * 64 + j * 8 + (lane & 7);
                int col = kt * 16 + ((lane >> 3) & 1) * 8;
                unsigned bh0, bh1, bl0, bl1;
                ldmx2(bh0, bh1, smem_u32(khi + row * QSTR + col));
                ldmx2(bl0, bl1, smem_u32(klo + row * QSTR + col));
                mma_bf16(s[j], qh[kt], bh0, bh1);
                mma_bf16(s[j], qh[kt], bl0, bl1);
                mma_bf16(s[j], ql[kt], bh0, bh1);
            }
        }
        // ---- online softmax (rows r=lane/4 and r+8) ----
        float bm_lo = -1e30f, bm_hi = -1e30f;
        #pragma unroll
        for (int j = 0; j < 8; j++) {
            bm_lo = fmaxf(bm_lo, fmaxf(s[j][0], s[j][1]));
            bm_hi = fmaxf(bm_hi, fmaxf(s[j][2], s[j][3]));
        }
        bm_lo = fmaxf(bm_lo, __shfl_xor_sync(0xFFFFFFFFu, bm_lo, 1));
        bm_lo = fmaxf(bm_lo, __shfl_xor_sync(0xFFFFFFFFu, bm_lo, 2));
        bm_hi = fmaxf(bm_hi, __shfl_xor_sync(0xFFFFFFFFu, bm_hi, 1));
        bm_hi = fmaxf(bm_hi, __shfl_xor_sync(0xFFFFFFFFu, bm_hi, 2));
        float nm_lo = fmaxf(m_lo, bm_lo);
        float nm_hi = fmaxf(m_hi, bm_hi);
        float corr_lo = exp2f(m_lo - nm_lo);
        float corr_hi = exp2f(m_hi - nm_hi);
        m_lo = nm_lo; m_hi = nm_hi;
        sum_lo *= corr_lo; sum_hi *= corr_hi;
        #pragma unroll
        for (int dn = 0; dn < 4; dn++) {
            o[dn][0] *= corr_lo; o[dn][1] *= corr_lo;
            o[dn][2] *= corr_hi; o[dn][3] *= corr_hi;
        }
        unsigned pl[8], ph[8];
        #pragma unroll
        for (int j = 0; j < 8; j++) {
            float p0 = exp2f(s[j][0] - m_lo);
            float p1 = exp2f(s[j][1] - m_lo);
            float p2 = exp2f(s[j][2] - m_hi);
            float p3 = exp2f(s[j][3] - m_hi);
            sum_lo += p0 + p1;
            sum_hi += p2 + p3;
            pl[j] = pack_bf16x2(p0, p1);
            ph[j] = pack_bf16x2(p2, p3);
        }
        // ---- O += P·V ----
        #pragma unroll
        for (int kt = 0; kt < 4; kt++) {
            unsigned a[4] = {pl[2 * kt], ph[2 * kt], pl[2 * kt + 1], ph[2 * kt + 1]};
            #pragma unroll
            for (int dn = 0; dn < 4; dn++) {
                int drow = dn * 8 + (lane & 7);
                int kcol = kb * 64 + kt * 16 + ((lane >> 3) & 1) * 8;
                unsigned b0, b1;
                ldmx2(b0, b1, smem_u32(vt + drow * VSTR + kcol));
                mma_bf16(o[dn], a, b0, b1);
            }
        }
    }

    // ---- finalize ----
    sum_lo += __shfl_xor_sync(0xFFFFFFFFu, sum_lo, 1);
    sum_lo += __shfl_xor_sync(0xFFFFFFFFu, sum_lo, 2);
    sum_hi += __shfl_xor_sync(0xFFFFFFFFu, sum_hi, 1);
    sum_hi += __shfl_xor_sync(0xFFFFFFFFu, sum_hi, 2);
    float inv_lo = 1.f / sum_lo;
    float inv_hi = 1.f / sum_hi;
    int r = lane >> 2, cc = (lane & 3) * 2;
    int q0 = qt * 128 + m0 + r;
    #pragma unroll
    for (int dn = 0; dn < 4; dn++) {
        int d = dn * 8 + cc;
        float2 t0 = make_float2(o[dn][0] * inv_lo, o[dn][1] * inv_lo);
        float2 t1 = make_float2(o[dn][2] * inv_hi, o[dn][3] * inv_hi);
        *(float2*)(out + ((size_t)(b * NPIX + q0)) * C + head * HD + d) = t0;
        *(float2*)(out + ((size_t)(b * NPIX + q0 + 8)) * C + head * HD + d) = t1;
    }
}

// ---------------- launch ------------------------------------------------------
extern "C" void kernel_launch(void* const* d_in, const int* in_sizes, int n_in,
                              void* d_out, int out_size) {
    int base = (n_in >= 19) ? 3 : 1;
    const float* x      = (const float*)d_in[0];
    const float* Wq     = (const float*)d_in[base + 0];
    const float* bq     = (const float*)d_in[base + 1];
    const float* Wkv    = (const float*)d_in[base + 2];
    const float* bkv    = (const float*)d_in[base + 3];
    const float* sr_w1  = (const float*)d_in[base + 4];
    const float* bn1g   = (const float*)d_in[base + 5];
    const float* bn1b   = (const float*)d_in[base + 6];
    const float* bn1m   = (const float*)d_in[base + 7];
    const float* bn1v   = (const float*)d_in[base + 8];
    const float* sr_w2  = (const float*)d_in[base + 9];
    const float* bn2g   = (const float*)d_in[base + 10];
    const float* bn2b   = (const float*)d_in[base + 11];
    const float* bn2m   = (const float*)d_in[base + 12];
    const float* bn2v   = (const float*)d_in[base + 13];
    const float* lw     = (const float*)d_in[base + 14];
    const float* lb     = (const float*)d_in[base + 15];
    float* out = (float*)d_out;

    float* gq  = nullptr; cudaGetSymbolAddress((void**)&gq,  g_q);
    float* gkv = nullptr; cudaGetSymbolAddress((void**)&gkv, g_kv2);
    float* gkp = nullptr; cudaGetSymbolAddress((void**)&gkp, g_kvp);

    cudaFuncSetAttribute(attn_kernel,
                         cudaFuncAttributeMaxDynamicSharedMemorySize, ATTN_SMEM);

    gemm_xw_kernel<<<dim3(BATCH * NPIX / 64, C / 64), 256>>>(x, Wq, bq, gq, C);
    srconv_kernel<<<dim3(MRED, BATCH), 256>>>(x, sr_w1, bn1g, bn1b, bn1m, bn1v,
                                              sr_w2, bn2g, bn2b, bn2m, bn2v);
    localconv_kernel<<<dim3(MRED, BATCH), 256>>>(lw, lb);
    gemm_xw_kernel<<<dim3(BATCH * MRED / 64, 2 * C / 64), 256>>>(gkv, Wkv, bkv,
                                                                 gkp, 2 * C);
    attn_kernel<<<dim3(NPIX / 128, HEADS, BATCH), 256, ATTN_SMEM>>>(out);
}

// round 6
// speedup vs baseline: 3.2663x; 1.3299x over previous
#include <cuda_runtime.h>
#include <cuda_bf16.h>
#include <math.h>
#include <string.h>

#define BATCH 8
#define C 256
#define NPIX 4096
#define HIMG 64
#define WIMG 64
#define MRED 256
#define HEADS 8
#define HD 32
#define ATTN_SCALE 0.17677669529663687f
#define EPS 1e-5f

// ---------------- scratch ----------------------------------------------------
__device__ float g_q[BATCH * NPIX * C];       // (b*n, c)
__device__ float g_kvred[BATCH * MRED * C];   // (b, m, c)
__device__ float g_kv2[BATCH * MRED * C];     // (b, m, c)
__device__ float g_kvp[BATCH * MRED * 2 * C]; // (b, m, 512)

// ---------------- helpers ------------------------------------------------------
__device__ __forceinline__ unsigned smem_u32(const void* p) {
    unsigned a;
    asm("{ .reg .u64 t; cvta.to.shared.u64 t, %1; cvt.u32.u64 %0, t; }"
        : "=r"(a) : "l"(p));
    return a;
}

__device__ __forceinline__ void ldmx4(unsigned* r, unsigned addr) {
    asm volatile("ldmatrix.sync.aligned.m8n8.x4.shared.b16 {%0,%1,%2,%3}, [%4];"
                 : "=r"(r[0]), "=r"(r[1]), "=r"(r[2]), "=r"(r[3]) : "r"(addr));
}
__device__ __forceinline__ void ldmx2(unsigned& b0, unsigned& b1, unsigned addr) {
    asm volatile("ldmatrix.sync.aligned.m8n8.x2.shared.b16 {%0,%1}, [%2];"
                 : "=r"(b0), "=r"(b1) : "r"(addr));
}
__device__ __forceinline__ void mma_bf16(float* c, const unsigned* a,
                                         unsigned b0, unsigned b1) {
    asm volatile(
        "mma.sync.aligned.m16n8k16.row.col.f32.bf16.bf16.f32 "
        "{%0,%1,%2,%3}, {%4,%5,%6,%7}, {%8,%9}, {%0,%1,%2,%3};"
        : "+f"(c[0]), "+f"(c[1]), "+f"(c[2]), "+f"(c[3])
        : "r"(a[0]), "r"(a[1]), "r"(a[2]), "r"(a[3]), "r"(b0), "r"(b1));
}
__device__ __forceinline__ unsigned pack_bf16x2(float lo, float hi) {
    unsigned d;
    asm("cvt.rn.bf16x2.f32 %0, %1, %2;" : "=r"(d) : "f"(hi), "f"(lo));
    return d;
}

// ---------------- HMMA GEMM (3-term bf16 split): Out = X·W^T + bias ----------
// X: (M,256) fp32 K-major; W: (N,256) fp32 K-major. Block tile 128x128, KC=32.
#define GSTR 40
__global__ __launch_bounds__(256, 2) void gemm_mma_kernel(
    const float* __restrict__ X, const float* __restrict__ W,
    const float* __restrict__ bias, float* __restrict__ Out, int ncols) {
    __shared__ __nv_bfloat16 xhi[128 * GSTR], xlo[128 * GSTR];
    __shared__ __nv_bfloat16 whi[128 * GSTR], wlo[128 * GSTR];
    int tid = threadIdx.x, lane = tid & 31, w = tid >> 5;
    int bm = blockIdx.x * 128, bn = blockIdx.y * 128;
    int wm = (w & 3) * 32, wn = (w >> 2) * 64;

    float acc[2][8][4];
    #pragma unroll
    for (int mt = 0; mt < 2; mt++)
        #pragma unroll
        for (int nt = 0; nt < 8; nt++)
            #pragma unroll
            for (int q = 0; q < 4; q++) acc[mt][nt][q] = 0.f;

    for (int kc = 0; kc < C; kc += 32) {
        // stage X and W chunk (128 rows x 32 k each), hi/lo split
        #pragma unroll
        for (int i = tid; i < 128 * 16; i += 256) {
            int r = i >> 4, k2 = (i & 15) * 2;
            float2 xv = *(const float2*)(X + (size_t)(bm + r) * C + kc + k2);
            __nv_bfloat16 h0 = __float2bfloat16(xv.x);
            __nv_bfloat16 h1 = __float2bfloat16(xv.y);
            xhi[r * GSTR + k2] = h0;
            xhi[r * GSTR + k2 + 1] = h1;
            xlo[r * GSTR + k2] = __float2bfloat16(xv.x - __bfloat162float(h0));
            xlo[r * GSTR + k2 + 1] = __float2bfloat16(xv.y - __bfloat162float(h1));
            float2 wv = *(const float2*)(W + (size_t)(bn + r) * C + kc + k2);
            __nv_bfloat16 g0 = __float2bfloat16(wv.x);
            __nv_bfloat16 g1 = __float2bfloat16(wv.y);
            whi[r * GSTR + k2] = g0;
            whi[r * GSTR + k2 + 1] = g1;
            wlo[r * GSTR + k2] = __float2bfloat16(wv.x - __bfloat162float(g0));
            wlo[r * GSTR + k2 + 1] = __float2bfloat16(wv.y - __bfloat162float(g1));
        }
        __syncthreads();

        #pragma unroll
        for (int ks = 0; ks < 2; ks++) {
            int arow = wm + (lane & 15);
            int acol = ks * 16 + (lane >> 4) * 8;
            unsigned ah[2][4], al[2][4];
            #pragma unroll
            for (int mt = 0; mt < 2; mt++) {
                ldmx4(ah[mt], smem_u32(xhi + (arow + mt * 16) * GSTR + acol));
                ldmx4(al[mt], smem_u32(xlo + (arow + mt * 16) * GSTR + acol));
            }
            unsigned bh[8][2], bl[8][2];
            #pragma unroll
            for (int nt4 = 0; nt4 < 4; nt4++) {
                int brow = wn + nt4 * 16 + (lane & 15);
                unsigned t[4];
                ldmx4(t, smem_u32(whi + brow * GSTR + acol));
                bh[nt4 * 2][0] = t[0]; bh[nt4 * 2][1] = t[2];
                bh[nt4 * 2 + 1][0] = t[1]; bh[nt4 * 2 + 1][1] = t[3];
                ldmx4(t, smem_u32(wlo + brow * GSTR + acol));
                bl[nt4 * 2][0] = t[0]; bl[nt4 * 2][1] = t[2];
                bl[nt4 * 2 + 1][0] = t[1]; bl[nt4 * 2 + 1][1] = t[3];
            }
            #pragma unroll
            for (int mt = 0; mt < 2; mt++)
                #pragma unroll
                for (int nt = 0; nt < 8; nt++) {
                    mma_bf16(acc[mt][nt], ah[mt], bh[nt][0], bh[nt][1]);
                    mma_bf16(acc[mt][nt], ah[mt], bl[nt][0], bl[nt][1]);
                    mma_bf16(acc[mt][nt], al[mt], bh[nt][0], bh[nt][1]);
                }
        }
        __syncthreads();
    }

    // store (+bias)
    int r_in = (lane >> 2), c_in = (lane & 3) * 2;
    #pragma unroll
    for (int mt = 0; mt < 2; mt++) {
        #pragma unroll
        for (int nt = 0; nt < 8; nt++) {
            int col = bn + wn + nt * 8 + c_in;
            float b0 = bias[col], b1 = bias[col + 1];
            int row0 = bm + wm + mt * 16 + r_in;
            float2 v0 = make_float2(acc[mt][nt][0] + b0, acc[mt][nt][1] + b1);
            float2 v1 = make_float2(acc[mt][nt][2] + b0, acc[mt][nt][3] + b1);
            *(float2*)(Out + (size_t)row0 * ncols + col) = v0;
            *(float2*)(Out + (size_t)(row0 + 8) * ncols + col) = v1;
        }
    }
}

// ---------------- SR conv: reads x (b,n,c) directly, writes (b,m,c) ----------
__global__ __launch_bounds__(256) void srconv_kernel(
    const float* __restrict__ x, const float* __restrict__ w7,
    const float* __restrict__ g1, const float* __restrict__ b1,
    const float* __restrict__ m1, const float* __restrict__ v1,
    const float* __restrict__ w2,
    const float* __restrict__ g2, const float* __restrict__ b2,
    const float* __restrict__ m2, const float* __restrict__ v2) {
    int opix = blockIdx.x;
    int b = blockIdx.y;
    int c = threadIdx.x;
    int oy = opix >> 4, ox = opix & 15;
    const float* xb = x + (size_t)b * NPIX * C;
    float s = 0.f;
    #pragma unroll
    for (int ky = 0; ky < 7; ky++) {
        int iy = oy * 4 - 3 + ky;
        if (iy < 0 || iy >= HIMG) continue;
        #pragma unroll
        for (int kx = 0; kx < 7; kx++) {
            int ix = ox * 4 - 3 + kx;
            if (ix < 0 || ix >= WIMG) continue;
            s += xb[(size_t)(iy * WIMG + ix) * C + c] * w7[c * 49 + ky * 7 + kx];
        }
    }
    float sc1 = g1[c] * rsqrtf(v1[c] + EPS);
    float val = s * sc1 + (b1[c] - m1[c] * sc1);
    val = 0.5f * val * (1.f + erff(val * 0.7071067811865476f));
    val *= w2[c];
    float sc2 = g2[c] * rsqrtf(v2[c] + EPS);
    val = val * sc2 + (b2[c] - m2[c] * sc2);
    g_kvred[((size_t)b * MRED + opix) * C + c] = val;
}

// ---------------- local 3x3 dwconv + bias + residual, (b,m,c) layout ---------
__global__ __launch_bounds__(256) void localconv_kernel(
    const float* __restrict__ lw, const float* __restrict__ lb) {
    int opix = blockIdx.x;
    int b = blockIdx.y;
    int c = threadIdx.x;
    int y = opix >> 4, xq = opix & 15;
    const float* src = g_kvred + (size_t)b * MRED * C;
    float ctr = src[(size_t)opix * C + c];
    float s = lb[c] + ctr;
    #pragma unroll
    for (int dy = -1; dy <= 1; dy++) {
        int yy = y + dy;
        if (yy < 0 || yy >= 16) continue;
        #pragma unroll
        for (int dx = -1; dx <= 1; dx++) {
            int xx = xq + dx;
            if (xx < 0 || xx >= 16) continue;
            s += src[(size_t)(yy * 16 + xx) * C + c] * lw[c * 9 + (dy + 1) * 3 + (dx + 1)];
        }
    }
    g_kv2[((size_t)b * MRED + opix) * C + c] = s;
}

// ---------------- flash attention via mma.sync bf16 ---------------------------
#define QSTR 40
#define VSTR 264
#define SM_QHI 0
#define SM_QLO (SM_QHI + 128 * QSTR)
#define SM_KHI (SM_QLO + 128 * QSTR)
#define SM_KLO (SM_KHI + 256 * QSTR)
#define SM_VT  (SM_KLO + 256 * QSTR)
#define ATTN_SMEM ((SM_VT + 32 * VSTR) * 2)

__global__ __launch_bounds__(256) void attn_kernel(float* __restrict__ out) {
    extern __shared__ __nv_bfloat16 sm[];
    __nv_bfloat16* qhi = sm + SM_QHI;
    __nv_bfloat16* qlo = sm + SM_QLO;
    __nv_bfloat16* khi = sm + SM_KHI;
    __nv_bfloat16* klo = sm + SM_KLO;
    __nv_bfloat16* vt  = sm + SM_VT;

    int tid = threadIdx.x, lane = tid & 31, w = tid >> 5;
    int qt = blockIdx.x, head = blockIdx.y, b = blockIdx.z;
    const float QSC = ATTN_SCALE * 1.4426950408889634f;

    for (int i = tid; i < 128 * 16; i += 256) {
        int n = i >> 4, d2 = (i & 15) * 2;
        float2 v = *(const float2*)(g_q + ((size_t)(b * NPIX + qt * 128 + n)) * C
                                    + head * HD + d2);
        float a0 = v.x * QSC, a1 = v.y * QSC;
        __nv_bfloat16 h0 = __float2bfloat16(a0);
        __nv_bfloat16 h1 = __float2bfloat16(a1);
        qhi[n * QSTR + d2] = h0;
        qhi[n * QSTR + d2 + 1] = h1;
        qlo[n * QSTR + d2] = __float2bfloat16(a0 - __bfloat162float(h0));
        qlo[n * QSTR + d2 + 1] = __float2bfloat16(a1 - __bfloat162float(h1));
    }
    for (int i = tid; i < 256 * 16; i += 256) {
        int m = i >> 4, d2 = (i & 15) * 2;
        const float* kr = g_kvp + ((size_t)(b * MRED + m)) * (2 * C) + head * HD;
        float2 kv = *(const float2*)(kr + d2);
        __nv_bfloat16 h0 = __float2bfloat16(kv.x);
        __nv_bfloat16 h1 = __float2bfloat16(kv.y);
        khi[m * QSTR + d2] = h0;
        khi[m * QSTR + d2 + 1] = h1;
        klo[m * QSTR + d2] = __float2bfloat16(kv.x - __bfloat162float(h0));
        klo[m * QSTR + d2 + 1] = __float2bfloat16(kv.y - __bfloat162float(h1));
        float2 vv = *(const float2*)(kr + C + d2);
        vt[d2 * VSTR + m] = __float2bfloat16(vv.x);
        vt[(d2 + 1) * VSTR + m] = __float2bfloat16(vv.y);
    }
    __syncthreads();

    int m0 = w * 16;
    unsigned qh[2][4], ql[2][4];
    #pragma unroll
    for (int kt = 0; kt < 2; kt++) {
        int row = m0 + (lane & 15);
        int col = kt * 16 + (lane >> 4) * 8;
        ldmx4(qh[kt], smem_u32(qhi + row * QSTR + col));
        ldmx4(ql[kt], smem_u32(qlo + row * QSTR + col));
    }

    float m_lo = -1e30f, m_hi = -1e30f, sum_lo = 0.f, sum_hi = 0.f;
    float o[4][4];
    #pragma unroll
    for (int i = 0; i < 4; i++)
        #pragma unroll
        for (int j = 0; j < 4; j++) o[i][j] = 0.f;

    #pragma unroll
    for (int kb = 0; kb < 4; kb++) {
        float s[8][4];
        #pragma unroll
        for (int j = 0; j < 8; j++)
            #pragma unroll
            for (int q = 0; q < 4; q++) s[j][q] = 0.f;
        #pragma unroll
        for (int kt = 0; kt < 2; kt++) {
            #pragma unroll
            for (int j = 0; j < 8; j++) {
                int row = kb * 64 + j * 8 + (lane & 7);
                int col = kt * 16 + ((lane >> 3) & 1) * 8;
                unsigned bh0, bh1, bl0, bl1;
                ldmx2(bh0, bh1, smem_u32(khi + row * QSTR + col));
                ldmx2(bl0, bl1, smem_u32(klo + row * QSTR + col));
                mma_bf16(s[j], qh[kt], bh0, bh1);
                mma_bf16(s[j], qh[kt], bl0, bl1);
                mma_bf16(s[j], ql[kt], bh0, bh1);
            }
        }
        float bm_lo = -1e30f, bm_hi = -1e30f;
        #pragma unroll
        for (int j = 0; j < 8; j++) {
            bm_lo = fmaxf(bm_lo, fmaxf(s[j][0], s[j][1]));
            bm_hi = fmaxf(bm_hi, fmaxf(s[j][2], s[j][3]));
        }
        bm_lo = fmaxf(bm_lo, __shfl_xor_sync(0xFFFFFFFFu, bm_lo, 1));
        bm_lo = fmaxf(bm_lo, __shfl_xor_sync(0xFFFFFFFFu, bm_lo, 2));
        bm_hi = fmaxf(bm_hi, __shfl_xor_sync(0xFFFFFFFFu, bm_hi, 1));
        bm_hi = fmaxf(bm_hi, __shfl_xor_sync(0xFFFFFFFFu, bm_hi, 2));
        float nm_lo = fmaxf(m_lo, bm_lo);
        float nm_hi = fmaxf(m_hi, bm_hi);
        float corr_lo = exp2f(m_lo - nm_lo);
        float corr_hi = exp2f(m_hi - nm_hi);
        m_lo = nm_lo; m_hi = nm_hi;
        sum_lo *= corr_lo; sum_hi *= corr_hi;
        #pragma unroll
        for (int dn = 0; dn < 4; dn++) {
            o[dn][0] *= corr_lo; o[dn][1] *= corr_lo;
            o[dn][2] *= corr_hi; o[dn][3] *= corr_hi;
        }
        unsigned pl[8], ph[8];
        #pragma unroll
        for (int j = 0; j < 8; j++) {
            float p0 = exp2f(s[j][0] - m_lo);
            float p1 = exp2f(s[j][1] - m_lo);
            float p2 = exp2f(s[j][2] - m_hi);
            float p3 = exp2f(s[j][3] - m_hi);
            sum_lo += p0 + p1;
            sum_hi += p2 + p3;
            pl[j] = pack_bf16x2(p0, p1);
            ph[j] = pack_bf16x2(p2, p3);
        }
        #pragma unroll
        for (int kt = 0; kt < 4; kt++) {
            unsigned a[4] = {pl[2 * kt], ph[2 * kt], pl[2 * kt + 1], ph[2 * kt + 1]};
            #pragma unroll
            for (int dn = 0; dn < 4; dn++) {
                int drow = dn * 8 + (lane & 7);
                int kcol = kb * 64 + kt * 16 + ((lane >> 3) & 1) * 8;
                unsigned b0, b1;
                ldmx2(b0, b1, smem_u32(vt + drow * VSTR + kcol));
                mma_bf16(o[dn], a, b0, b1);
            }
        }
    }

    sum_lo += __shfl_xor_sync(0xFFFFFFFFu, sum_lo, 1);
    sum_lo += __shfl_xor_sync(0xFFFFFFFFu, sum_lo, 2);
    sum_hi += __shfl_xor_sync(0xFFFFFFFFu, sum_hi, 1);
    sum_hi += __shfl_xor_sync(0xFFFFFFFFu, sum_hi, 2);
    float inv_lo = 1.f / sum_lo;
    float inv_hi = 1.f / sum_hi;
    int r = lane >> 2, cc = (lane & 3) * 2;
    int q0 = qt * 128 + m0 + r;
    #pragma unroll
    for (int dn = 0; dn < 4; dn++) {
        int d = dn * 8 + cc;
        float2 t0 = make_float2(o[dn][0] * inv_lo, o[dn][1] * inv_lo);
        float2 t1 = make_float2(o[dn][2] * inv_hi, o[dn][3] * inv_hi);
        *(float2*)(out + ((size_t)(b * NPIX + q0)) * C + head * HD + d) = t0;
        *(float2*)(out + ((size_t)(b * NPIX + q0 + 8)) * C + head * HD + d) = t1;
    }
}

// ---------------- launch ------------------------------------------------------
extern "C" void kernel_launch(void* const* d_in, const int* in_sizes, int n_in,
                              void* d_out, int out_size) {
    int base = (n_in >= 19) ? 3 : 1;
    const float* x      = (const float*)d_in[0];
    const float* Wq     = (const float*)d_in[base + 0];
    const float* bq     = (const float*)d_in[base + 1];
    const float* Wkv    = (const float*)d_in[base + 2];
    const float* bkv    = (const float*)d_in[base + 3];
    const float* sr_w1  = (const float*)d_in[base + 4];
    const float* bn1g   = (const float*)d_in[base + 5];
    const float* bn1b   = (const float*)d_in[base + 6];
    const float* bn1m   = (const float*)d_in[base + 7];
    const float* bn1v   = (const float*)d_in[base + 8];
    const float* sr_w2  = (const float*)d_in[base + 9];
    const float* bn2g   = (const float*)d_in[base + 10];
    const float* bn2b   = (const float*)d_in[base + 11];
    const float* bn2m   = (const float*)d_in[base + 12];
    const float* bn2v   = (const float*)d_in[base + 13];
    const float* lw     = (const float*)d_in[base + 14];
    const float* lb     = (const float*)d_in[base + 15];
    float* out = (float*)d_out;

    float* gq  = nullptr; cudaGetSymbolAddress((void**)&gq,  g_q);
    float* gkv = nullptr; cudaGetSymbolAddress((void**)&gkv, g_kv2);
    float* gkp = nullptr; cudaGetSymbolAddress((void**)&gkp, g_kvp);

    cudaFuncSetAttribute(attn_kernel,
                         cudaFuncAttributeMaxDynamicSharedMemorySize, ATTN_SMEM);

    gemm_mma_kernel<<<dim3(BATCH * NPIX / 128, C / 128), 256>>>(x, Wq, bq, gq, C);
    srconv_kernel<<<dim3(MRED, BATCH), 256>>>(x, sr_w1, bn1g, bn1b, bn1m, bn1v,
                                              sr_w2, bn2g, bn2b, bn2m, bn2v);
    localconv_kernel<<<dim3(MRED, BATCH), 256>>>(lw, lb);
    gemm_mma_kernel<<<dim3(BATCH * MRED / 128, 2 * C / 128), 256>>>(gkv, Wkv, bkv,
                                                                    gkp, 2 * C);
    attn_kernel<<<dim3(NPIX / 128, HEADS, BATCH), 256, ATTN_SMEM>>>(out);
}

// round 7
// speedup vs baseline: 3.3003x; 1.0104x over previous
#include <cuda_runtime.h>
#include <cuda_bf16.h>
#include <math.h>
#include <string.h>

#define BATCH 8
#define C 256
#define NPIX 4096
#define HIMG 64
#define WIMG 64
#define MRED 256
#define HEADS 8
#define HD 32
#define ATTN_SCALE 0.17677669529663687f
#define EPS 1e-5f

// ---------------- scratch ----------------------------------------------------
__device__ float g_q[BATCH * NPIX * C];       // (b*n, c)
__device__ float g_kvred[BATCH * MRED * C];   // (b, m, c)
__device__ float g_kv2[BATCH * MRED * C];     // (b, m, c)
__device__ float g_kvp[BATCH * MRED * 2 * C]; // (b, m, 512)

// ---------------- helpers ------------------------------------------------------
__device__ __forceinline__ unsigned smem_u32(const void* p) {
    unsigned a;
    asm("{ .reg .u64 t; cvta.to.shared.u64 t, %1; cvt.u32.u64 %0, t; }"
        : "=r"(a) : "l"(p));
    return a;
}

__device__ __forceinline__ void ldmx4(unsigned* r, unsigned addr) {
    asm volatile("ldmatrix.sync.aligned.m8n8.x4.shared.b16 {%0,%1,%2,%3}, [%4];"
                 : "=r"(r[0]), "=r"(r[1]), "=r"(r[2]), "=r"(r[3]) : "r"(addr));
}
__device__ __forceinline__ void mma_bf16(float* c, const unsigned* a,
                                         unsigned b0, unsigned b1) {
    asm volatile(
        "mma.sync.aligned.m16n8k16.row.col.f32.bf16.bf16.f32 "
        "{%0,%1,%2,%3}, {%4,%5,%6,%7}, {%8,%9}, {%0,%1,%2,%3};"
        : "+f"(c[0]), "+f"(c[1]), "+f"(c[2]), "+f"(c[3])
        : "r"(a[0]), "r"(a[1]), "r"(a[2]), "r"(a[3]), "r"(b0), "r"(b1));
}
__device__ __forceinline__ unsigned pack_bf16x2(float lo, float hi) {
    unsigned d;
    asm("cvt.rn.bf16x2.f32 %0, %1, %2;" : "=r"(d) : "f"(hi), "f"(lo));
    return d;
}
__device__ __forceinline__ void split_store(__nv_bfloat16* hi, __nv_bfloat16* lo,
                                            int idx, float a0, float a1) {
    __nv_bfloat16 h0 = __float2bfloat16(a0);
    __nv_bfloat16 h1 = __float2bfloat16(a1);
    *(__nv_bfloat162*)(hi + idx) = __nv_bfloat162(h0, h1);
    *(__nv_bfloat162*)(lo + idx) = __nv_bfloat162(
        __float2bfloat16(a0 - __bfloat162float(h0)),
        __float2bfloat16(a1 - __bfloat162float(h1)));
}

// ---------------- HMMA GEMM (3-term bf16 split): Out = X·W^T + bias ----------
// Tile 64(M) x 128(N), K-chunk 32. 8 warps, warp tile 16x64.
#define GSTR 40
__global__ __launch_bounds__(256) void gemm_mma_kernel(
    const float* __restrict__ X, const float* __restrict__ W,
    const float* __restrict__ bias, float* __restrict__ Out, int ncols) {
    __shared__ __nv_bfloat16 xhi[64 * GSTR], xlo[64 * GSTR];
    __shared__ __nv_bfloat16 whi[128 * GSTR], wlo[128 * GSTR];
    int tid = threadIdx.x, lane = tid & 31, w = tid >> 5;
    int bm = blockIdx.x * 64, bn = blockIdx.y * 128;
    int wm = (w & 3) * 16, wn = (w >> 2) * 64;

    float acc[8][4];
    #pragma unroll
    for (int nt = 0; nt < 8; nt++)
        #pragma unroll
        for (int q = 0; q < 4; q++) acc[nt][q] = 0.f;

    for (int kc = 0; kc < C; kc += 32) {
        #pragma unroll
        for (int i = tid; i < 64 * 16; i += 256) {
            int r = i >> 4, k2 = (i & 15) * 2;
            float2 xv = *(const float2*)(X + (size_t)(bm + r) * C + kc + k2);
            split_store(xhi, xlo, r * GSTR + k2, xv.x, xv.y);
        }
        #pragma unroll
        for (int i = tid; i < 128 * 16; i += 256) {
            int r = i >> 4, k2 = (i & 15) * 2;
            float2 wv = *(const float2*)(W + (size_t)(bn + r) * C + kc + k2);
            split_store(whi, wlo, r * GSTR + k2, wv.x, wv.y);
        }
        __syncthreads();

        #pragma unroll
        for (int ks = 0; ks < 2; ks++) {
            int acol = ks * 16 + (lane >> 4) * 8;
            int arow = wm + (lane & 15);
            unsigned ah[4], al[4];
            ldmx4(ah, smem_u32(xhi + arow * GSTR + acol));
            ldmx4(al, smem_u32(xlo + arow * GSTR + acol));
            unsigned bh[8][2], bl[8][2];
            #pragma unroll
            for (int nt4 = 0; nt4 < 4; nt4++) {
                int brow = wn + nt4 * 16 + (lane & 15);
                unsigned t[4];
                ldmx4(t, smem_u32(whi + brow * GSTR + acol));
                bh[nt4 * 2][0] = t[0]; bh[nt4 * 2][1] = t[2];
                bh[nt4 * 2 + 1][0] = t[1]; bh[nt4 * 2 + 1][1] = t[3];
                ldmx4(t, smem_u32(wlo + brow * GSTR + acol));
                bl[nt4 * 2][0] = t[0]; bl[nt4 * 2][1] = t[2];
                bl[nt4 * 2 + 1][0] = t[1]; bl[nt4 * 2 + 1][1] = t[3];
            }
            #pragma unroll
            for (int nt = 0; nt < 8; nt++) {
                mma_bf16(acc[nt], ah, bh[nt][0], bh[nt][1]);
                mma_bf16(acc[nt], ah, bl[nt][0], bl[nt][1]);
                mma_bf16(acc[nt], al, bh[nt][0], bh[nt][1]);
            }
        }
        __syncthreads();
    }

    int r_in = (lane >> 2), c_in = (lane & 3) * 2;
    #pragma unroll
    for (int nt = 0; nt < 8; nt++) {
        int col = bn + wn + nt * 8 + c_in;
        float b0 = bias[col], b1 = bias[col + 1];
        int row0 = bm + wm + r_in;
        float2 v0 = make_float2(acc[nt][0] + b0, acc[nt][1] + b1);
        float2 v1 = make_float2(acc[nt][2] + b0, acc[nt][3] + b1);
        *(float2*)(Out + (size_t)row0 * ncols + col) = v0;
        *(float2*)(Out + (size_t)(row0 + 8) * ncols + col) = v1;
    }
}

// ---------------- SR conv: reads x (b,n,c) directly, writes (b,m,c) ----------
__global__ __launch_bounds__(256) void srconv_kernel(
    const float* __restrict__ x, const float* __restrict__ w7,
    const float* __restrict__ g1, const float* __restrict__ b1,
    const float* __restrict__ m1, const float* __restrict__ v1,
    const float* __restrict__ w2,
    const float* __restrict__ g2, const float* __restrict__ b2,
    const float* __restrict__ m2, const float* __restrict__ v2) {
    int opix = blockIdx.x;
    int b = blockIdx.y;
    int c = threadIdx.x;
    int oy = opix >> 4, ox = opix & 15;
    const float* xb = x + (size_t)b * NPIX * C;
    float s = 0.f;
    #pragma unroll
    for (int ky = 0; ky < 7; ky++) {
        int iy = oy * 4 - 3 + ky;
        if (iy < 0 || iy >= HIMG) continue;
        #pragma unroll
        for (int kx = 0; kx < 7; kx++) {
            int ix = ox * 4 - 3 + kx;
            if (ix < 0 || ix >= WIMG) continue;
            s += xb[(size_t)(iy * WIMG + ix) * C + c] * w7[c * 49 + ky * 7 + kx];
        }
    }
    float sc1 = g1[c] * rsqrtf(v1[c] + EPS);
    float val = s * sc1 + (b1[c] - m1[c] * sc1);
    val = 0.5f * val * (1.f + erff(val * 0.7071067811865476f));
    val *= w2[c];
    float sc2 = g2[c] * rsqrtf(v2[c] + EPS);
    val = val * sc2 + (b2[c] - m2[c] * sc2);
    g_kvred[((size_t)b * MRED + opix) * C + c] = val;
}

// ---------------- local 3x3 dwconv + bias + residual, (b,m,c) layout ---------
__global__ __launch_bounds__(256) void localconv_kernel(
    const float* __restrict__ lw, const float* __restrict__ lb) {
    int opix = blockIdx.x;
    int b = blockIdx.y;
    int c = threadIdx.x;
    int y = opix >> 4, xq = opix & 15;
    const float* src = g_kvred + (size_t)b * MRED * C;
    float ctr = src[(size_t)opix * C + c];
    float s = lb[c] + ctr;
    #pragma unroll
    for (int dy = -1; dy <= 1; dy++) {
        int yy = y + dy;
        if (yy < 0 || yy >= 16) continue;
        #pragma unroll
        for (int dx = -1; dx <= 1; dx++) {
            int xx = xq + dx;
            if (xx < 0 || xx >= 16) continue;
            s += src[(size_t)(yy * 16 + xx) * C + c] * lw[c * 9 + (dy + 1) * 3 + (dx + 1)];
        }
    }
    g_kv2[((size_t)b * MRED + opix) * C + c] = s;
}

// ---------------- flash attention via mma.sync bf16 ---------------------------
#define QSTR 40
#define VSTR 264
#define SM_QHI 0
#define SM_QLO (SM_QHI + 128 * QSTR)
#define SM_KHI (SM_QLO + 128 * QSTR)
#define SM_KLO (SM_KHI + 256 * QSTR)
#define SM_VT  (SM_KLO + 256 * QSTR)
#define ATTN_SMEM ((SM_VT + 32 * VSTR) * 2)

__global__ __launch_bounds__(256) void attn_kernel(float* __restrict__ out) {
    extern __shared__ __nv_bfloat16 sm[];
    __nv_bfloat16* qhi = sm + SM_QHI;
    __nv_bfloat16* qlo = sm + SM_QLO;
    __nv_bfloat16* khi = sm + SM_KHI;
    __nv_bfloat16* klo = sm + SM_KLO;
    __nv_bfloat16* vt  = sm + SM_VT;

    int tid = threadIdx.x, lane = tid & 31, w = tid >> 5;
    int qt = blockIdx.x, head = blockIdx.y, b = blockIdx.z;
    const float QSC = ATTN_SCALE * 1.4426950408889634f;

    for (int i = tid; i < 128 * 16; i += 256) {
        int n = i >> 4, d2 = (i & 15) * 2;
        float2 v = *(const float2*)(g_q + ((size_t)(b * NPIX + qt * 128 + n)) * C
                                    + head * HD + d2);
        split_store(qhi, qlo, n * QSTR + d2, v.x * QSC, v.y * QSC);
    }
    for (int i = tid; i < 256 * 16; i += 256) {
        int m = i >> 4, d2 = (i & 15) * 2;
        const float* kr = g_kvp + ((size_t)(b * MRED + m)) * (2 * C) + head * HD;
        float2 kv = *(const float2*)(kr + d2);
        split_store(khi, klo, m * QSTR + d2, kv.x, kv.y);
        float2 vv = *(const float2*)(kr + C + d2);
        vt[d2 * VSTR + m] = __float2bfloat16(vv.x);
        vt[(d2 + 1) * VSTR + m] = __float2bfloat16(vv.y);
    }
    __syncthreads();

    int m0 = w * 16;
    unsigned qh[2][4], ql[2][4];
    #pragma unroll
    for (int kt = 0; kt < 2; kt++) {
        int row = m0 + (lane & 15);
        int col = kt * 16 + (lane >> 4) * 8;
        ldmx4(qh[kt], smem_u32(qhi + row * QSTR + col));
        ldmx4(ql[kt], smem_u32(qlo + row * QSTR + col));
    }

    float m_lo = -1e30f, m_hi = -1e30f, sum_lo = 0.f, sum_hi = 0.f;
    float o[4][4];
    #pragma unroll
    for (int i = 0; i < 4; i++)
        #pragma unroll
        for (int j = 0; j < 4; j++) o[i][j] = 0.f;

    #pragma unroll
    for (int kb = 0; kb < 4; kb++) {
        float s[8][4];
        #pragma unroll
        for (int j = 0; j < 8; j++)
            #pragma unroll
            for (int q = 0; q < 4; q++) s[j][q] = 0.f;
        #pragma unroll
        for (int kt = 0; kt < 2; kt++) {
            int col = kt * 16 + (lane >> 4) * 8;
            #pragma unroll
            for (int jj = 0; jj < 4; jj++) {
                int row = kb * 64 + jj * 16 + (lane & 15);
                unsigned th[4], tl[4];
                ldmx4(th, smem_u32(khi + row * QSTR + col));
                ldmx4(tl, smem_u32(klo + row * QSTR + col));
                mma_bf16(s[2 * jj], qh[kt], th[0], th[2]);
                mma_bf16(s[2 * jj], qh[kt], tl[0], tl[2]);
                mma_bf16(s[2 * jj], ql[kt], th[0], th[2]);
                mma_bf16(s[2 * jj + 1], qh[kt], th[1], th[3]);
                mma_bf16(s[2 * jj + 1], qh[kt], tl[1], tl[3]);
                mma_bf16(s[2 * jj + 1], ql[kt], th[1], th[3]);
            }
        }
        float bm_lo = -1e30f, bm_hi = -1e30f;
        #pragma unroll
        for (int j = 0; j < 8; j++) {
            bm_lo = fmaxf(bm_lo, fmaxf(s[j][0], s[j][1]));
            bm_hi = fmaxf(bm_hi, fmaxf(s[j][2], s[j][3]));
        }
        bm_lo = fmaxf(bm_lo, __shfl_xor_sync(0xFFFFFFFFu, bm_lo, 1));
        bm_lo = fmaxf(bm_lo, __shfl_xor_sync(0xFFFFFFFFu, bm_lo, 2));
        bm_hi = fmaxf(bm_hi, __shfl_xor_sync(0xFFFFFFFFu, bm_hi, 1));
        bm_hi = fmaxf(bm_hi, __shfl_xor_sync(0xFFFFFFFFu, bm_hi, 2));
        float nm_lo = fmaxf(m_lo, bm_lo);
        float nm_hi = fmaxf(m_hi, bm_hi);
        float corr_lo = exp2f(m_lo - nm_lo);
        float corr_hi = exp2f(m_hi - nm_hi);
        m_lo = nm_lo; m_hi = nm_hi;
        sum_lo *= corr_lo; sum_hi *= corr_hi;
        #pragma unroll
        for (int dn = 0; dn < 4; dn++) {
            o[dn][0] *= corr_lo; o[dn][1] *= corr_lo;
            o[dn][2] *= corr_hi; o[dn][3] *= corr_hi;
        }
        unsigned pl[8], ph[8];
        #pragma unroll
        for (int j = 0; j < 8; j++) {
            float p0 = exp2f(s[j][0] - m_lo);
            float p1 = exp2f(s[j][1] - m_lo);
            float p2 = exp2f(s[j][2] - m_hi);
            float p3 = exp2f(s[j][3] - m_hi);
            sum_lo += p0 + p1;
            sum_hi += p2 + p3;
            pl[j] = pack_bf16x2(p0, p1);
            ph[j] = pack_bf16x2(p2, p3);
        }
        #pragma unroll
        for (int kt = 0; kt < 4; kt++) {
            unsigned a[4] = {pl[2 * kt], ph[2 * kt], pl[2 * kt + 1], ph[2 * kt + 1]};
            int kcol = kb * 64 + kt * 16 + (lane >> 4) * 8;
            #pragma unroll
            for (int dn2 = 0; dn2 < 2; dn2++) {
                int drow = dn2 * 16 + (lane & 15);
                unsigned t[4];
                ldmx4(t, smem_u32(vt + drow * VSTR + kcol));
                mma_bf16(o[2 * dn2], a, t[0], t[2]);
                mma_bf16(o[2 * dn2 + 1], a, t[1], t[3]);
            }
        }
    }

    sum_lo += __shfl_xor_sync(0xFFFFFFFFu, sum_lo, 1);
    sum_lo += __shfl_xor_sync(0xFFFFFFFFu, sum_lo, 2);
    sum_hi += __shfl_xor_sync(0xFFFFFFFFu, sum_hi, 1);
    sum_hi += __shfl_xor_sync(0xFFFFFFFFu, sum_hi, 2);
    float inv_lo = 1.f / sum_lo;
    float inv_hi = 1.f / sum_hi;
    int r = lane >> 2, cc = (lane & 3) * 2;
    int q0 = qt * 128 + m0 + r;
    #pragma unroll
    for (int dn = 0; dn < 4; dn++) {
        int d = dn * 8 + cc;
        float2 t0 = make_float2(o[dn][0] * inv_lo, o[dn][1] * inv_lo);
        float2 t1 = make_float2(o[dn][2] * inv_hi, o[dn][3] * inv_hi);
        *(float2*)(out + ((size_t)(b * NPIX + q0)) * C + head * HD + d) = t0;
        *(float2*)(out + ((size_t)(b * NPIX + q0 + 8)) * C + head * HD + d) = t1;
    }
}

// ---------------- launch ------------------------------------------------------
extern "C" void kernel_launch(void* const* d_in, const int* in_sizes, int n_in,
                              void* d_out, int out_size) {
    int base = (n_in >= 19) ? 3 : 1;
    const float* x      = (const float*)d_in[0];
    const float* Wq     = (const float*)d_in[base + 0];
    const float* bq     = (const float*)d_in[base + 1];
    const float* Wkv    = (const float*)d_in[base + 2];
    const float* bkv    = (const float*)d_in[base + 3];
    const float* sr_w1  = (const float*)d_in[base + 4];
    const float* bn1g   = (const float*)d_in[base + 5];
    const float* bn1b   = (const float*)d_in[base + 6];
    const float* bn1m   = (const float*)d_in[base + 7];
    const float* bn1v   = (const float*)d_in[base + 8];
    const float* sr_w2  = (const float*)d_in[base + 9];
    const float* bn2g   = (const float*)d_in[base + 10];
    const float* bn2b   = (const float*)d_in[base + 11];
    const float* bn2m   = (const float*)d_in[base + 12];
    const float* bn2v   = (const float*)d_in[base + 13];
    const float* lw     = (const float*)d_in[base + 14];
    const float* lb     = (const float*)d_in[base + 15];
    float* out = (float*)d_out;

    float* gq  = nullptr; cudaGetSymbolAddress((void**)&gq,  g_q);
    float* gkv = nullptr; cudaGetSymbolAddress((void**)&gkv, g_kv2);
    float* gkp = nullptr; cudaGetSymbolAddress((void**)&gkp, g_kvp);

    cudaFuncSetAttribute(attn_kernel,
                         cudaFuncAttributeMaxDynamicSharedMemorySize, ATTN_SMEM);

    gemm_mma_kernel<<<dim3(BATCH * NPIX / 64, C / 128), 256>>>(x, Wq, bq, gq, C);
    srconv_kernel<<<dim3(MRED, BATCH), 256>>>(x, sr_w1, bn1g, bn1b, bn1m, bn1v,
                                              sr_w2, bn2g, bn2b, bn2m, bn2v);
    localconv_kernel<<<dim3(MRED, BATCH), 256>>>(lw, lb);
    gemm_mma_kernel<<<dim3(BATCH * MRED / 64, 2 * C / 128), 256>>>(gkv, Wkv, bkv,
                                                                   gkp, 2 * C);
    attn_kernel<<<dim3(NPIX / 128, HEADS, BATCH), 256, ATTN_SMEM>>>(out);
}

// round 8
// speedup vs baseline: 3.3008x; 1.0001x over previous
#include <cuda_runtime.h>
#include <cuda_bf16.h>
#include <math.h>
#include <string.h>

#define BATCH 8
#define C 256
#define NPIX 4096
#define HIMG 64
#define WIMG 64
#define MRED 256
#define HEADS 8
#define HD 32
#define ATTN_SCALE 0.17677669529663687f
#define EPS 1e-5f

// ---------------- scratch ----------------------------------------------------
__device__ float g_q[BATCH * NPIX * C];       // (b*n, c)
__device__ float g_kvred[BATCH * MRED * C];   // (b, m, c)
__device__ float g_kvp[BATCH * MRED * 2 * C]; // (b, m, 512)
// pre-split bf16 operands
__device__ __nv_bfloat16 g_xh[BATCH * NPIX * C], g_xl[BATCH * NPIX * C];
__device__ __nv_bfloat16 g_wqh[C * C], g_wql[C * C];
__device__ __nv_bfloat16 g_wkvh[2 * C * C], g_wkvl[2 * C * C];
__device__ __nv_bfloat16 g_kv2h[BATCH * MRED * C], g_kv2l[BATCH * MRED * C];

// ---------------- helpers ------------------------------------------------------
__device__ __forceinline__ unsigned smem_u32(const void* p) {
    unsigned a;
    asm("{ .reg .u64 t; cvta.to.shared.u64 t, %1; cvt.u32.u64 %0, t; }"
        : "=r"(a) : "l"(p));
    return a;
}
__device__ __forceinline__ void cp16(unsigned dst, const void* src) {
    asm volatile("cp.async.ca.shared.global [%0], [%1], 16;"
                 :: "r"(dst), "l"(src));
}
#define CP_COMMIT() asm volatile("cp.async.commit_group;" ::: "memory")
#define CP_WAIT(n)  asm volatile("cp.async.wait_group %0;" :: "n"(n) : "memory")

__device__ __forceinline__ void ldmx4(unsigned* r, unsigned addr) {
    asm volatile("ldmatrix.sync.aligned.m8n8.x4.shared.b16 {%0,%1,%2,%3}, [%4];"
                 : "=r"(r[0]), "=r"(r[1]), "=r"(r[2]), "=r"(r[3]) : "r"(addr));
}
__device__ __forceinline__ void mma_bf16(float* c, const unsigned* a,
                                         unsigned b0, unsigned b1) {
    asm volatile(
        "mma.sync.aligned.m16n8k16.row.col.f32.bf16.bf16.f32 "
        "{%0,%1,%2,%3}, {%4,%5,%6,%7}, {%8,%9}, {%0,%1,%2,%3};"
        : "+f"(c[0]), "+f"(c[1]), "+f"(c[2]), "+f"(c[3])
        : "r"(a[0]), "r"(a[1]), "r"(a[2]), "r"(a[3]), "r"(b0), "r"(b1));
}
__device__ __forceinline__ unsigned pack_bf16x2(float lo, float hi) {
    unsigned d;
    asm("cvt.rn.bf16x2.f32 %0, %1, %2;" : "=r"(d) : "f"(hi), "f"(lo));
    return d;
}
__device__ __forceinline__ void split_store(__nv_bfloat16* hi, __nv_bfloat16* lo,
                                            int idx, float a0, float a1) {
    __nv_bfloat16 h0 = __float2bfloat16(a0);
    __nv_bfloat16 h1 = __float2bfloat16(a1);
    *(__nv_bfloat162*)(hi + idx) = __nv_bfloat162(h0, h1);
    *(__nv_bfloat162*)(lo + idx) = __nv_bfloat162(
        __float2bfloat16(a0 - __bfloat162float(h0)),
        __float2bfloat16(a1 - __bfloat162float(h1)));
}

// ---------------- fp32 -> bf16 hi/lo split (n multiple of 4) -----------------
__global__ __launch_bounds__(256) void split_kernel(
    const float* __restrict__ src, __nv_bfloat16* __restrict__ hi,
    __nv_bfloat16* __restrict__ lo, int n4) {
    int i = blockIdx.x * 256 + threadIdx.x;
    if (i >= n4) return;
    float4 v = ((const float4*)src)[i];
    split_store(hi, lo, 4 * i, v.x, v.y);
    split_store(hi, lo, 4 * i + 2, v.z, v.w);
}

// ---------------- HMMA GEMM, pre-split bf16 + cp.async double buffer ----------
// Tile 64(M) x 128(N), K-chunk 32, 8 warps (warp tile 16x64).
#define GSTR 40
struct GemmStage {
    __nv_bfloat16 xh[64 * GSTR], xl[64 * GSTR];
    __nv_bfloat16 wh[128 * GSTR], wl[128 * GSTR];
};

__global__ __launch_bounds__(256, 2) void gemm_mma_kernel(
    const __nv_bfloat16* __restrict__ Xh, const __nv_bfloat16* __restrict__ Xl,
    const __nv_bfloat16* __restrict__ Wh, const __nv_bfloat16* __restrict__ Wl,
    const float* __restrict__ bias, float* __restrict__ Out, int ncols) {
    __shared__ GemmStage st[2];
    int tid = threadIdx.x, lane = tid & 31, w = tid >> 5;
    int bm = blockIdx.x * 64, bn = blockIdx.y * 128;
    int wm = (w & 3) * 16, wn = (w >> 2) * 64;

    int lr = tid >> 2, lch = (tid & 3) * 8;   // row / bf16-col offset for loads

    float acc[8][4];
    #pragma unroll
    for (int nt = 0; nt < 8; nt++)
        #pragma unroll
        for (int q = 0; q < 4; q++) acc[nt][q] = 0.f;

    // stage loader: chunk kc (bf16 col offset), stage s
    #define LOAD_STAGE(s, kc) do {                                             \
        cp16(smem_u32(st[s].xh + lr * GSTR + lch),                             \
             Xh + (size_t)(bm + lr) * C + (kc) + lch);                         \
        cp16(smem_u32(st[s].xl + lr * GSTR + lch),                             \
             Xl + (size_t)(bm + lr) * C + (kc) + lch);                         \
        cp16(smem_u32(st[s].wh + lr * GSTR + lch),                             \
             Wh + (size_t)(bn + lr) * C + (kc) + lch);                         \
        cp16(smem_u32(st[s].wl + lr * GSTR + lch),                             \
             Wl + (size_t)(bn + lr) * C + (kc) + lch);                         \
        cp16(smem_u32(st[s].wh + (lr + 64) * GSTR + lch),                      \
             Wh + (size_t)(bn + lr + 64) * C + (kc) + lch);                    \
        cp16(smem_u32(st[s].wl + (lr + 64) * GSTR + lch),                      \
             Wl + (size_t)(bn + lr + 64) * C + (kc) + lch);                    \
    } while (0)

    LOAD_STAGE(0, 0);
    CP_COMMIT();

    #pragma unroll
    for (int kk = 0; kk < 8; kk++) {
        int s = kk & 1;
        if (kk < 7) {
            LOAD_STAGE(s ^ 1, (kk + 1) * 32);
            CP_COMMIT();
            CP_WAIT(1);
        } else {
            CP_WAIT(0);
        }
        __syncthreads();

        #pragma unroll
        for (int ks = 0; ks < 2; ks++) {
            int acol = ks * 16 + (lane >> 4) * 8;
            int arow = wm + (lane & 15);
            unsigned ah[4], al[4];
            ldmx4(ah, smem_u32(st[s].xh + arow * GSTR + acol));
            ldmx4(al, smem_u32(st[s].xl + arow * GSTR + acol));
            unsigned bh[8][2], bl[8][2];
            #pragma unroll
            for (int nt4 = 0; nt4 < 4; nt4++) {
                int brow = wn + nt4 * 16 + (lane & 15);
                unsigned t[4];
                ldmx4(t, smem_u32(st[s].wh + brow * GSTR + acol));
                bh[nt4 * 2][0] = t[0]; bh[nt4 * 2][1] = t[2];
                bh[nt4 * 2 + 1][0] = t[1]; bh[nt4 * 2 + 1][1] = t[3];
                ldmx4(t, smem_u32(st[s].wl + brow * GSTR + acol));
                bl[nt4 * 2][0] = t[0]; bl[nt4 * 2][1] = t[2];
                bl[nt4 * 2 + 1][0] = t[1]; bl[nt4 * 2 + 1][1] = t[3];
            }
            #pragma unroll
            for (int nt = 0; nt < 8; nt++) {
                mma_bf16(acc[nt], ah, bh[nt][0], bh[nt][1]);
                mma_bf16(acc[nt], ah, bl[nt][0], bl[nt][1]);
                mma_bf16(acc[nt], al, bh[nt][0], bh[nt][1]);
            }
        }
        __syncthreads();
    }

    int r_in = (lane >> 2), c_in = (lane & 3) * 2;
    #pragma unroll
    for (int nt = 0; nt < 8; nt++) {
        int col = bn + wn + nt * 8 + c_in;
        float b0 = bias[col], b1 = bias[col + 1];
        int row0 = bm + wm + r_in;
        float2 v0 = make_float2(acc[nt][0] + b0, acc[nt][1] + b1);
        float2 v1 = make_float2(acc[nt][2] + b0, acc[nt][3] + b1);
        *(float2*)(Out + (size_t)row0 * ncols + col) = v0;
        *(float2*)(Out + (size_t)(row0 + 8) * ncols + col) = v1;
    }
}

// ---------------- SR conv: reads x (b,n,c) directly, writes (b,m,c) ----------
__global__ __launch_bounds__(256) void srconv_kernel(
    const float* __restrict__ x, const float* __restrict__ w7,
    const float* __restrict__ g1, const float* __restrict__ b1,
    const float* __restrict__ m1, const float* __restrict__ v1,
    const float* __restrict__ w2,
    const float* __restrict__ g2, const float* __restrict__ b2,
    const float* __restrict__ m2, const float* __restrict__ v2) {
    int opix = blockIdx.x;
    int b = blockIdx.y;
    int c = threadIdx.x;
    int oy = opix >> 4, ox = opix & 15;
    const float* xb = x + (size_t)b * NPIX * C;
    float s = 0.f;
    #pragma unroll
    for (int ky = 0; ky < 7; ky++) {
        int iy = oy * 4 - 3 + ky;
        if (iy < 0 || iy >= HIMG) continue;
        #pragma unroll
        for (int kx = 0; kx < 7; kx++) {
            int ix = ox * 4 - 3 + kx;
            if (ix < 0 || ix >= WIMG) continue;
            s += xb[(size_t)(iy * WIMG + ix) * C + c] * w7[c * 49 + ky * 7 + kx];
        }
    }
    float sc1 = g1[c] * rsqrtf(v1[c] + EPS);
    float val = s * sc1 + (b1[c] - m1[c] * sc1);
    val = 0.5f * val * (1.f + erff(val * 0.7071067811865476f));
    val *= w2[c];
    float sc2 = g2[c] * rsqrtf(v2[c] + EPS);
    val = val * sc2 + (b2[c] - m2[c] * sc2);
    g_kvred[((size_t)b * MRED + opix) * C + c] = val;
}

// ---------------- local 3x3 dwconv + residual -> bf16 hi/lo -------------------
__global__ __launch_bounds__(256) void localconv_kernel(
    const float* __restrict__ lw, const float* __restrict__ lb) {
    int opix = blockIdx.x;
    int b = blockIdx.y;
    int c = threadIdx.x * 2;   // each thread does 2 adjacent channels
    int y = opix >> 4, xq = opix & 15;
    const float* src = g_kvred + (size_t)b * MRED * C;
    float s0 = lb[c]     + src[(size_t)opix * C + c];
    float s1 = lb[c + 1] + src[(size_t)opix * C + c + 1];
    #pragma unroll
    for (int dy = -1; dy <= 1; dy++) {
        int yy = y + dy;
        if (yy < 0 || yy >= 16) continue;
        #pragma unroll
        for (int dx = -1; dx <= 1; dx++) {
            int xx = xq + dx;
            if (xx < 0 || xx >= 16) continue;
            float w0 = lw[c * 9 + (dy + 1) * 3 + (dx + 1)];
            float w1 = lw[(c + 1) * 9 + (dy + 1) * 3 + (dx + 1)];
            s0 += src[(size_t)(yy * 16 + xx) * C + c] * w0;
            s1 += src[(size_t)(yy * 16 + xx) * C + c + 1] * w1;
        }
    }
    split_store(g_kv2h, g_kv2l, ((size_t)b * MRED + opix) * C + c, s0, s1);
}

// ---------------- flash attention via mma.sync bf16 ---------------------------
#define QSTR 40
#define VSTR 264
#define SM_QHI 0
#define SM_QLO (SM_QHI + 128 * QSTR)
#define SM_KHI (SM_QLO + 128 * QSTR)
#define SM_KLO (SM_KHI + 256 * QSTR)
#define SM_VT  (SM_KLO + 256 * QSTR)
#define ATTN_SMEM ((SM_VT + 32 * VSTR) * 2)

__global__ __launch_bounds__(256) void attn_kernel(float* __restrict__ out) {
    extern __shared__ __nv_bfloat16 sm[];
    __nv_bfloat16* qhi = sm + SM_QHI;
    __nv_bfloat16* qlo = sm + SM_QLO;
    __nv_bfloat16* khi = sm + SM_KHI;
    __nv_bfloat16* klo = sm + SM_KLO;
    __nv_bfloat16* vt  = sm + SM_VT;

    int tid = threadIdx.x, lane = tid & 31, w = tid >> 5;
    int qt = blockIdx.x, head = blockIdx.y, b = blockIdx.z;
    const float QSC = ATTN_SCALE * 1.4426950408889634f;

    for (int i = tid; i < 128 * 16; i += 256) {
        int n = i >> 4, d2 = (i & 15) * 2;
        float2 v = *(const float2*)(g_q + ((size_t)(b * NPIX + qt * 128 + n)) * C
                                    + head * HD + d2);
        split_store(qhi, qlo, n * QSTR + d2, v.x * QSC, v.y * QSC);
    }
    for (int i = tid; i < 256 * 16; i += 256) {
        int m = i >> 4, d2 = (i & 15) * 2;
        const float* kr = g_kvp + ((size_t)(b * MRED + m)) * (2 * C) + head * HD;
        float2 kv = *(const float2*)(kr + d2);
        split_store(khi, klo, m * QSTR + d2, kv.x, kv.y);
        float2 vv = *(const float2*)(kr + C + d2);
        vt[d2 * VSTR + m] = __float2bfloat16(vv.x);
        vt[(d2 + 1) * VSTR + m] = __float2bfloat16(vv.y);
    }
    __syncthreads();

    int m0 = w * 16;
    unsigned qh[2][4], ql[2][4];
    #pragma unroll
    for (int kt = 0; kt < 2; kt++) {
        int row = m0 + (lane & 15);
        int col = kt * 16 + (lane >> 4) * 8;
        ldmx4(qh[kt], smem_u32(qhi + row * QSTR + col));
        ldmx4(ql[kt], smem_u32(qlo + row * QSTR + col));
    }

    float m_lo = -1e30f, m_hi = -1e30f, sum_lo = 0.f, sum_hi = 0.f;
    float o[4][4];
    #pragma unroll
    for (int i = 0; i < 4; i++)
        #pragma unroll
        for (int j = 0; j < 4; j++) o[i][j] = 0.f;

    #pragma unroll
    for (int kb = 0; kb < 4; kb++) {
        float s[8][4];
        #pragma unroll
        for (int j = 0; j < 8; j++)
            #pragma unroll
            for (int q = 0; q < 4; q++) s[j][q] = 0.f;
        #pragma unroll
        for (int kt = 0; kt < 2; kt++) {
            int col = kt * 16 + (lane >> 4) * 8;
            #pragma unroll
            for (int jj = 0; jj < 4; jj++) {
                int row = kb * 64 + jj * 16 + (lane & 15);
                unsigned th[4], tl[4];
                ldmx4(th, smem_u32(khi + row * QSTR + col));
                ldmx4(tl, smem_u32(klo + row * QSTR + col));
                mma_bf16(s[2 * jj], qh[kt], th[0], th[2]);
                mma_bf16(s[2 * jj], qh[kt], tl[0], tl[2]);
                mma_bf16(s[2 * jj], ql[kt], th[0], th[2]);
                mma_bf16(s[2 * jj + 1], qh[kt], th[1], th[3]);
                mma_bf16(s[2 * jj + 1], qh[kt], tl[1], tl[3]);
                mma_bf16(s[2 * jj + 1], ql[kt], th[1], th[3]);
            }
        }
        float bm_lo = -1e30f, bm_hi = -1e30f;
        #pragma unroll
        for (int j = 0; j < 8; j++) {
            bm_lo = fmaxf(bm_lo, fmaxf(s[j][0], s[j][1]));
            bm_hi = fmaxf(bm_hi, fmaxf(s[j][2], s[j][3]));
        }
        bm_lo = fmaxf(bm_lo, __shfl_xor_sync(0xFFFFFFFFu, bm_lo, 1));
        bm_lo = fmaxf(bm_lo, __shfl_xor_sync(0xFFFFFFFFu, bm_lo, 2));
        bm_hi = fmaxf(bm_hi, __shfl_xor_sync(0xFFFFFFFFu, bm_hi, 1));
        bm_hi = fmaxf(bm_hi, __shfl_xor_sync(0xFFFFFFFFu, bm_hi, 2));
        float nm_lo = fmaxf(m_lo, bm_lo);
        float nm_hi = fmaxf(m_hi, bm_hi);
        float corr_lo = exp2f(m_lo - nm_lo);
        float corr_hi = exp2f(m_hi - nm_hi);
        m_lo = nm_lo; m_hi = nm_hi;
        sum_lo *= corr_lo; sum_hi *= corr_hi;
        #pragma unroll
        for (int dn = 0; dn < 4; dn++) {
            o[dn][0] *= corr_lo; o[dn][1] *= corr_lo;
            o[dn][2] *= corr_hi; o[dn][3] *= corr_hi;
        }
        unsigned pl[8], ph[8];
        #pragma unroll
        for (int j = 0; j < 8; j++) {
            float p0 = exp2f(s[j][0] - m_lo);
            float p1 = exp2f(s[j][1] - m_lo);
            float p2 = exp2f(s[j][2] - m_hi);
            float p3 = exp2f(s[j][3] - m_hi);
            sum_lo += p0 + p1;
            sum_hi += p2 + p3;
            pl[j] = pack_bf16x2(p0, p1);
            ph[j] = pack_bf16x2(p2, p3);
        }
        #pragma unroll
        for (int kt = 0; kt < 4; kt++) {
            unsigned a[4] = {pl[2 * kt], ph[2 * kt], pl[2 * kt + 1], ph[2 * kt + 1]};
            int kcol = kb * 64 + kt * 16 + (lane >> 4) * 8;
            #pragma unroll
            for (int dn2 = 0; dn2 < 2; dn2++) {
                int drow = dn2 * 16 + (lane & 15);
                unsigned t[4];
                ldmx4(t, smem_u32(vt + drow * VSTR + kcol));
                mma_bf16(o[2 * dn2], a, t[0], t[2]);
                mma_bf16(o[2 * dn2 + 1], a, t[1], t[3]);
            }
        }
    }

    sum_lo += __shfl_xor_sync(0xFFFFFFFFu, sum_lo, 1);
    sum_lo += __shfl_xor_sync(0xFFFFFFFFu, sum_lo, 2);
    sum_hi += __shfl_xor_sync(0xFFFFFFFFu, sum_hi, 1);
    sum_hi += __shfl_xor_sync(0xFFFFFFFFu, sum_hi, 2);
    float inv_lo = 1.f / sum_lo;
    float inv_hi = 1.f / sum_hi;
    int r = lane >> 2, cc = (lane & 3) * 2;
    int q0 = qt * 128 + m0 + r;
    #pragma unroll
    for (int dn = 0; dn < 4; dn++) {
        int d = dn * 8 + cc;
        float2 t0 = make_float2(o[dn][0] * inv_lo, o[dn][1] * inv_lo);
        float2 t1 = make_float2(o[dn][2] * inv_hi, o[dn][3] * inv_hi);
        *(float2*)(out + ((size_t)(b * NPIX + q0)) * C + head * HD + d) = t0;
        *(float2*)(out + ((size_t)(b * NPIX + q0 + 8)) * C + head * HD + d) = t1;
    }
}

// ---------------- launch ------------------------------------------------------
extern "C" void kernel_launch(void* const* d_in, const int* in_sizes, int n_in,
                              void* d_out, int out_size) {
    int base = (n_in >= 19) ? 3 : 1;
    const float* x      = (const float*)d_in[0];
    const float* Wq     = (const float*)d_in[base + 0];
    const float* bq     = (const float*)d_in[base + 1];
    const float* Wkv    = (const float*)d_in[base + 2];
    const float* bkv    = (const float*)d_in[base + 3];
    const float* sr_w1  = (const float*)d_in[base + 4];
    const float* bn1g   = (const float*)d_in[base + 5];
    const float* bn1b   = (const float*)d_in[base + 6];
    const float* bn1m   = (const float*)d_in[base + 7];
    const float* bn1v   = (const float*)d_in[base + 8];
    const float* sr_w2  = (const float*)d_in[base + 9];
    const float* bn2g   = (const float*)d_in[base + 10];
    const float* bn2b   = (const float*)d_in[base + 11];
    const float* bn2m   = (const float*)d_in[base + 12];
    const float* bn2v   = (const float*)d_in[base + 13];
    const float* lw     = (const float*)d_in[base + 14];
    const float* lb     = (const float*)d_in[base + 15];
    float* out = (float*)d_out;

    float* gq = nullptr;  cudaGetSymbolAddress((void**)&gq, g_q);
    float* gkp = nullptr; cudaGetSymbolAddress((void**)&gkp, g_kvp);
    __nv_bfloat16 *xh, *xl, *wqh, *wql, *wkvh, *wkvl, *kv2h, *kv2l;
    cudaGetSymbolAddress((void**)&xh, g_xh);
    cudaGetSymbolAddress((void**)&xl, g_xl);
    cudaGetSymbolAddress((void**)&wqh, g_wqh);
    cudaGetSymbolAddress((void**)&wql, g_wql);
    cudaGetSymbolAddress((void**)&wkvh, g_wkvh);
    cudaGetSymbolAddress((void**)&wkvl, g_wkvl);
    cudaGetSymbolAddress((void**)&kv2h, g_kv2h);
    cudaGetSymbolAddress((void**)&kv2l, g_kv2l);

    cudaFuncSetAttribute(attn_kernel,
                         cudaFuncAttributeMaxDynamicSharedMemorySize, ATTN_SMEM);

    // pre-split to bf16 hi/lo
    int nx4 = BATCH * NPIX * C / 4;
    split_kernel<<<(nx4 + 255) / 256, 256>>>(x, xh, xl, nx4);
    split_kernel<<<(C * C / 4 + 255) / 256, 256>>>(Wq, wqh, wql, C * C / 4);
    split_kernel<<<(2 * C * C / 4 + 255) / 256, 256>>>(Wkv, wkvh, wkvl,
                                                        2 * C * C / 4);

    gemm_mma_kernel<<<dim3(BATCH * NPIX / 64, C / 128), 256>>>(
        xh, xl, wqh, wql, bq, gq, C);
    srconv_kernel<<<dim3(MRED, BATCH), 256>>>(x, sr_w1, bn1g, bn1b, bn1m, bn1v,
                                              sr_w2, bn2g, bn2b, bn2m, bn2v);
    localconv_kernel<<<dim3(MRED, BATCH), 128>>>(lw, lb);
    gemm_mma_kernel<<<dim3(BATCH * MRED / 64, 2 * C / 128), 256>>>(
        kv2h, kv2l, wkvh, wkvl, bkv, gkp, 2 * C);
    attn_kernel<<<dim3(NPIX / 128, HEADS, BATCH), 256, ATTN_SMEM>>>(out);
}

// round 9
// speedup vs baseline: 3.4246x; 1.0375x over previous
#include <cuda_runtime.h>
#include <cuda_bf16.h>
#include <math.h>
#include <string.h>

#define BATCH 8
#define C 256
#define NPIX 4096
#define HIMG 64
#define WIMG 64
#define MRED 256
#define HEADS 8
#define HD 32
#define ATTN_SCALE 0.17677669529663687f
#define EPS 1e-5f

// ---------------- scratch ----------------------------------------------------
__device__ float g_q[BATCH * NPIX * C];       // (b*n, c)
__device__ float g_kvred[BATCH * MRED * C];   // (b, m, c)
__device__ float g_kvp[BATCH * MRED * 2 * C]; // (b, m, 512)
// pre-split bf16 operands
__device__ __nv_bfloat16 g_xh[BATCH * NPIX * C], g_xl[BATCH * NPIX * C];
__device__ __nv_bfloat16 g_wqh[C * C], g_wql[C * C];
__device__ __nv_bfloat16 g_wkvh[2 * C * C], g_wkvl[2 * C * C];
__device__ __nv_bfloat16 g_kv2h[BATCH * MRED * C], g_kv2l[BATCH * MRED * C];
// transposed conv weights [k][c]
__device__ float g_w7t[49 * C];
__device__ float g_lwt[9 * C];

// ---------------- helpers ------------------------------------------------------
__device__ __forceinline__ unsigned smem_u32(const void* p) {
    unsigned a;
    asm("{ .reg .u64 t; cvta.to.shared.u64 t, %1; cvt.u32.u64 %0, t; }"
        : "=r"(a) : "l"(p));
    return a;
}
__device__ __forceinline__ void cp16(unsigned dst, const void* src) {
    asm volatile("cp.async.ca.shared.global [%0], [%1], 16;"
                 :: "r"(dst), "l"(src));
}
#define CP_COMMIT() asm volatile("cp.async.commit_group;" ::: "memory")
#define CP_WAIT(n)  asm volatile("cp.async.wait_group %0;" :: "n"(n) : "memory")

__device__ __forceinline__ void ldmx4(unsigned* r, unsigned addr) {
    asm volatile("ldmatrix.sync.aligned.m8n8.x4.shared.b16 {%0,%1,%2,%3}, [%4];"
                 : "=r"(r[0]), "=r"(r[1]), "=r"(r[2]), "=r"(r[3]) : "r"(addr));
}
__device__ __forceinline__ void mma_bf16(float* c, const unsigned* a,
                                         unsigned b0, unsigned b1) {
    asm volatile(
        "mma.sync.aligned.m16n8k16.row.col.f32.bf16.bf16.f32 "
        "{%0,%1,%2,%3}, {%4,%5,%6,%7}, {%8,%9}, {%0,%1,%2,%3};"
        : "+f"(c[0]), "+f"(c[1]), "+f"(c[2]), "+f"(c[3])
        : "r"(a[0]), "r"(a[1]), "r"(a[2]), "r"(a[3]), "r"(b0), "r"(b1));
}
__device__ __forceinline__ unsigned pack_bf16x2(float lo, float hi) {
    unsigned d;
    asm("cvt.rn.bf16x2.f32 %0, %1, %2;" : "=r"(d) : "f"(hi), "f"(lo));
    return d;
}
__device__ __forceinline__ void split_store(__nv_bfloat16* hi, __nv_bfloat16* lo,
                                            int idx, float a0, float a1) {
    __nv_bfloat16 h0 = __float2bfloat16(a0);
    __nv_bfloat16 h1 = __float2bfloat16(a1);
    *(__nv_bfloat162*)(hi + idx) = __nv_bfloat162(h0, h1);
    *(__nv_bfloat162*)(lo + idx) = __nv_bfloat162(
        __float2bfloat16(a0 - __bfloat162float(h0)),
        __float2bfloat16(a1 - __bfloat162float(h1)));
}

// ---------------- fp32 -> bf16 hi/lo split -----------------------------------
__global__ __launch_bounds__(256) void split_kernel(
    const float* __restrict__ src, __nv_bfloat16* __restrict__ hi,
    __nv_bfloat16* __restrict__ lo, int n4) {
    int i = blockIdx.x * 256 + threadIdx.x;
    if (i >= n4) return;
    float4 v = ((const float4*)src)[i];
    split_store(hi, lo, 4 * i, v.x, v.y);
    split_store(hi, lo, 4 * i + 2, v.z, v.w);
}

// ---------------- transpose conv weights to [k][c] ----------------------------
__global__ __launch_bounds__(256) void wtr_kernel(const float* __restrict__ w7,
                                                  const float* __restrict__ lw) {
    int c = threadIdx.x;
    int k = blockIdx.x;
    if (k < 49) g_w7t[k * C + c] = w7[c * 49 + k];
    if (k < 9)  g_lwt[k * C + c] = lw[c * 9 + k];
}

// ---------------- HMMA GEMM, pre-split bf16 + cp.async double buffer ----------
// BM x 128 tile, K-chunk 32, 8 warps. BM=128 -> warp 32x64; BM=64 -> warp 16x64.
#define GSTR 40
template <int BM>
__global__ __launch_bounds__(256, 2) void gemm_mma_kernel(
    const __nv_bfloat16* __restrict__ Xh, const __nv_bfloat16* __restrict__ Xl,
    const __nv_bfloat16* __restrict__ Wh, const __nv_bfloat16* __restrict__ Wl,
    const float* __restrict__ bias, float* __restrict__ Out, int ncols) {
    constexpr int MT = BM / 64;                  // A-fragment sets per warp
    constexpr int SX = BM * GSTR;                // elems per x buffer
    constexpr int SW = 128 * GSTR;
    constexpr int STG = 2 * SX + 2 * SW;         // elems per stage
    extern __shared__ __nv_bfloat16 gsm[];

    int tid = threadIdx.x, lane = tid & 31, w = tid >> 5;
    int bm = blockIdx.x * BM, bn = blockIdx.y * 128;
    int wm = (w & 3) * (16 * MT), wn = (w >> 2) * 64;
    int lr = tid >> 2, lch = (tid & 3) * 8;

    float acc[MT][8][4];
    #pragma unroll
    for (int mt = 0; mt < MT; mt++)
        #pragma unroll
        for (int nt = 0; nt < 8; nt++)
            #pragma unroll
            for (int q = 0; q < 4; q++) acc[mt][nt][q] = 0.f;

    #define XH(s) (gsm + (s) * STG)
    #define XL(s) (gsm + (s) * STG + SX)
    #define WH(s) (gsm + (s) * STG + 2 * SX)
    #define WL(s) (gsm + (s) * STG + 2 * SX + SW)

    #define LOAD_STAGE(s, kc) do {                                            \
        _Pragma("unroll")                                                      \
        for (int rr = 0; rr < MT; rr++) {                                      \
            cp16(smem_u32(XH(s) + (lr + 64 * rr) * GSTR + lch),                \
                 Xh + (size_t)(bm + lr + 64 * rr) * C + (kc) + lch);           \
            cp16(smem_u32(XL(s) + (lr + 64 * rr) * GSTR + lch),                \
                 Xl + (size_t)(bm + lr + 64 * rr) * C + (kc) + lch);           \
        }                                                                      \
        _Pragma("unroll")                                                      \
        for (int rr = 0; rr < 2; rr++) {                                       \
            cp16(smem_u32(WH(s) + (lr + 64 * rr) * GSTR + lch),                \
                 Wh + (size_t)(bn + lr + 64 * rr) * C + (kc) + lch);           \
            cp16(smem_u32(WL(s) + (lr + 64 * rr) * GSTR + lch),                \
                 Wl + (size_t)(bn + lr + 64 * rr) * C + (kc) + lch);           \
        }                                                                      \
    } while (0)

    LOAD_STAGE(0, 0);
    CP_COMMIT();

    #pragma unroll
    for (int kk = 0; kk < 8; kk++) {
        int s = kk & 1;
        if (kk < 7) {
            LOAD_STAGE(s ^ 1, (kk + 1) * 32);
            CP_COMMIT();
            CP_WAIT(1);
        } else {
            CP_WAIT(0);
        }
        __syncthreads();

        #pragma unroll
        for (int ks = 0; ks < 2; ks++) {
            int acol = ks * 16 + (lane >> 4) * 8;
            int arow = wm + (lane & 15);
            unsigned ah[MT][4], al[MT][4];
            #pragma unroll
            for (int mt = 0; mt < MT; mt++) {
                ldmx4(ah[mt], smem_u32(XH(s) + (arow + mt * 16) * GSTR + acol));
                ldmx4(al[mt], smem_u32(XL(s) + (arow + mt * 16) * GSTR + acol));
            }
            unsigned bh[8][2], bl[8][2];
            #pragma unroll
            for (int nt4 = 0; nt4 < 4; nt4++) {
                int brow = wn + nt4 * 16 + (lane & 15);
                unsigned t[4];
                ldmx4(t, smem_u32(WH(s) + brow * GSTR + acol));
                bh[nt4 * 2][0] = t[0]; bh[nt4 * 2][1] = t[2];
                bh[nt4 * 2 + 1][0] = t[1]; bh[nt4 * 2 + 1][1] = t[3];
                ldmx4(t, smem_u32(WL(s) + brow * GSTR + acol));
                bl[nt4 * 2][0] = t[0]; bl[nt4 * 2][1] = t[2];
                bl[nt4 * 2 + 1][0] = t[1]; bl[nt4 * 2 + 1][1] = t[3];
            }
            #pragma unroll
            for (int mt = 0; mt < MT; mt++)
                #pragma unroll
                for (int nt = 0; nt < 8; nt++) {
                    mma_bf16(acc[mt][nt], ah[mt], bh[nt][0], bh[nt][1]);
                    mma_bf16(acc[mt][nt], ah[mt], bl[nt][0], bl[nt][1]);
                    mma_bf16(acc[mt][nt], al[mt], bh[nt][0], bh[nt][1]);
                }
        }
        __syncthreads();
    }

    int r_in = (lane >> 2), c_in = (lane & 3) * 2;
    #pragma unroll
    for (int mt = 0; mt < MT; mt++)
        #pragma unroll
        for (int nt = 0; nt < 8; nt++) {
            int col = bn + wn + nt * 8 + c_in;
            float b0 = bias[col], b1 = bias[col + 1];
            int row0 = bm + wm + mt * 16 + r_in;
            float2 v0 = make_float2(acc[mt][nt][0] + b0, acc[mt][nt][1] + b1);
            float2 v1 = make_float2(acc[mt][nt][2] + b0, acc[mt][nt][3] + b1);
            *(float2*)(Out + (size_t)row0 * ncols + col) = v0;
            *(float2*)(Out + (size_t)(row0 + 8) * ncols + col) = v1;
        }
    #undef LOAD_STAGE
    #undef XH
    #undef XL
    #undef WH
    #undef WL
}

// ---------------- SR conv (transposed weights) --------------------------------
__global__ __launch_bounds__(256) void srconv_kernel(
    const float* __restrict__ x,
    const float* __restrict__ g1, const float* __restrict__ b1,
    const float* __restrict__ m1, const float* __restrict__ v1,
    const float* __restrict__ w2,
    const float* __restrict__ g2, const float* __restrict__ b2,
    const float* __restrict__ m2, const float* __restrict__ v2) {
    int opix = blockIdx.x;
    int b = blockIdx.y;
    int c = threadIdx.x;
    int oy = opix >> 4, ox = opix & 15;
    const float* xb = x + (size_t)b * NPIX * C;
    float s = 0.f;
    #pragma unroll
    for (int ky = 0; ky < 7; ky++) {
        int iy = oy * 4 - 3 + ky;
        if (iy < 0 || iy >= HIMG) continue;
        #pragma unroll
        for (int kx = 0; kx < 7; kx++) {
            int ix = ox * 4 - 3 + kx;
            if (ix < 0 || ix >= WIMG) continue;
            s += xb[(size_t)(iy * WIMG + ix) * C + c] * g_w7t[(ky * 7 + kx) * C + c];
        }
    }
    float sc1 = g1[c] * rsqrtf(v1[c] + EPS);
    float val = s * sc1 + (b1[c] - m1[c] * sc1);
    val = 0.5f * val * (1.f + erff(val * 0.7071067811865476f));
    val *= w2[c];
    float sc2 = g2[c] * rsqrtf(v2[c] + EPS);
    val = val * sc2 + (b2[c] - m2[c] * sc2);
    g_kvred[((size_t)b * MRED + opix) * C + c] = val;
}

// ---------------- local 3x3 dwconv + residual -> bf16 hi/lo -------------------
__global__ __launch_bounds__(128) void localconv_kernel(
    const float* __restrict__ lb) {
    int opix = blockIdx.x;
    int b = blockIdx.y;
    int c = threadIdx.x * 2;
    int y = opix >> 4, xq = opix & 15;
    const float* src = g_kvred + (size_t)b * MRED * C;
    float2 ctr = *(const float2*)(src + (size_t)opix * C + c);
    float s0 = lb[c] + ctr.x;
    float s1 = lb[c + 1] + ctr.y;
    #pragma unroll
    for (int dy = -1; dy <= 1; dy++) {
        int yy = y + dy;
        if (yy < 0 || yy >= 16) continue;
        #pragma unroll
        for (int dx = -1; dx <= 1; dx++) {
            int xx = xq + dx;
            if (xx < 0 || xx >= 16) continue;
            float2 wv = *(const float2*)(g_lwt + ((dy + 1) * 3 + (dx + 1)) * C + c);
            float2 sv = *(const float2*)(src + (size_t)(yy * 16 + xx) * C + c);
            s0 += sv.x * wv.x;
            s1 += sv.y * wv.y;
        }
    }
    split_store(g_kv2h, g_kv2l, ((size_t)b * MRED + opix) * C + c, s0, s1);
}

// ---------------- flash attention via mma.sync bf16 ---------------------------
#define QSTR 40
#define VSTR 264
#define SM_QHI 0
#define SM_QLO (SM_QHI + 128 * QSTR)
#define SM_KHI (SM_QLO + 128 * QSTR)
#define SM_KLO (SM_KHI + 256 * QSTR)
#define SM_VT  (SM_KLO + 256 * QSTR)
#define ATTN_SMEM ((SM_VT + 32 * VSTR) * 2)

__global__ __launch_bounds__(256) void attn_kernel(float* __restrict__ out) {
    extern __shared__ __nv_bfloat16 sm[];
    __nv_bfloat16* qhi = sm + SM_QHI;
    __nv_bfloat16* qlo = sm + SM_QLO;
    __nv_bfloat16* khi = sm + SM_KHI;
    __nv_bfloat16* klo = sm + SM_KLO;
    __nv_bfloat16* vt  = sm + SM_VT;

    int tid = threadIdx.x, lane = tid & 31, w = tid >> 5;
    int qt = blockIdx.x, head = blockIdx.y, b = blockIdx.z;
    const float QSC = ATTN_SCALE * 1.4426950408889634f;

    for (int i = tid; i < 128 * 16; i += 256) {
        int n = i >> 4, d2 = (i & 15) * 2;
        float2 v = *(const float2*)(g_q + ((size_t)(b * NPIX + qt * 128 + n)) * C
                                    + head * HD + d2);
        split_store(qhi, qlo, n * QSTR + d2, v.x * QSC, v.y * QSC);
    }
    for (int i = tid; i < 256 * 16; i += 256) {
        int m = i >> 4, d2 = (i & 15) * 2;
        const float* kr = g_kvp + ((size_t)(b * MRED + m)) * (2 * C) + head * HD;
        float2 kv = *(const float2*)(kr + d2);
        split_store(khi, klo, m * QSTR + d2, kv.x, kv.y);
        float2 vv = *(const float2*)(kr + C + d2);
        vt[d2 * VSTR + m] = __float2bfloat16(vv.x);
        vt[(d2 + 1) * VSTR + m] = __float2bfloat16(vv.y);
    }
    __syncthreads();

    int m0 = w * 16;
    unsigned qh[2][4], ql[2][4];
    #pragma unroll
    for (int kt = 0; kt < 2; kt++) {
        int row = m0 + (lane & 15);
        int col = kt * 16 + (lane >> 4) * 8;
        ldmx4(qh[kt], smem_u32(qhi + row * QSTR + col));
        ldmx4(ql[kt], smem_u32(qlo + row * QSTR + col));
    }

    float m_lo = -1e30f, m_hi = -1e30f, sum_lo = 0.f, sum_hi = 0.f;
    float o[4][4];
    #pragma unroll
    for (int i = 0; i < 4; i++)
        #pragma unroll
        for (int j = 0; j < 4; j++) o[i][j] = 0.f;

    #pragma unroll
    for (int kb = 0; kb < 4; kb++) {
        float s[8][4];
        #pragma unroll
        for (int j = 0; j < 8; j++)
            #pragma unroll
            for (int q = 0; q < 4; q++) s[j][q] = 0.f;
        #pragma unroll
        for (int kt = 0; kt < 2; kt++) {
            int col = kt * 16 + (lane >> 4) * 8;
            #pragma unroll
            for (int jj = 0; jj < 4; jj++) {
                int row = kb * 64 + jj * 16 + (lane & 15);
                unsigned th[4], tl[4];
                ldmx4(th, smem_u32(khi + row * QSTR + col));
                ldmx4(tl, smem_u32(klo + row * QSTR + col));
                mma_bf16(s[2 * jj], qh[kt], th[0], th[2]);
                mma_bf16(s[2 * jj], qh[kt], tl[0], tl[2]);
                mma_bf16(s[2 * jj], ql[kt], th[0], th[2]);
                mma_bf16(s[2 * jj + 1], qh[kt], th[1], th[3]);
                mma_bf16(s[2 * jj + 1], qh[kt], tl[1], tl[3]);
                mma_bf16(s[2 * jj + 1], ql[kt], th[1], th[3]);
            }
        }
        float bm_lo = -1e30f, bm_hi = -1e30f;
        #pragma unroll
        for (int j = 0; j < 8; j++) {
            bm_lo = fmaxf(bm_lo, fmaxf(s[j][0], s[j][1]));
            bm_hi = fmaxf(bm_hi, fmaxf(s[j][2], s[j][3]));
        }
        bm_lo = fmaxf(bm_lo, __shfl_xor_sync(0xFFFFFFFFu, bm_lo, 1));
        bm_lo = fmaxf(bm_lo, __shfl_xor_sync(0xFFFFFFFFu, bm_lo, 2));
        bm_hi = fmaxf(bm_hi, __shfl_xor_sync(0xFFFFFFFFu, bm_hi, 1));
        bm_hi = fmaxf(bm_hi, __shfl_xor_sync(0xFFFFFFFFu, bm_hi, 2));
        float nm_lo = fmaxf(m_lo, bm_lo);
        float nm_hi = fmaxf(m_hi, bm_hi);
        float corr_lo = exp2f(m_lo - nm_lo);
        float corr_hi = exp2f(m_hi - nm_hi);
        m_lo = nm_lo; m_hi = nm_hi;
        sum_lo *= corr_lo; sum_hi *= corr_hi;
        #pragma unroll
        for (int dn = 0; dn < 4; dn++) {
            o[dn][0] *= corr_lo; o[dn][1] *= corr_lo;
            o[dn][2] *= corr_hi; o[dn][3] *= corr_hi;
        }
        unsigned pl[8], ph[8];
        #pragma unroll
        for (int j = 0; j < 8; j++) {
            float p0 = exp2f(s[j][0] - m_lo);
            float p1 = exp2f(s[j][1] - m_lo);
            float p2 = exp2f(s[j][2] - m_hi);
            float p3 = exp2f(s[j][3] - m_hi);
            sum_lo += p0 + p1;
            sum_hi += p2 + p3;
            pl[j] = pack_bf16x2(p0, p1);
            ph[j] = pack_bf16x2(p2, p3);
        }
        #pragma unroll
        for (int kt = 0; kt < 4; kt++) {
            unsigned a[4] = {pl[2 * kt], ph[2 * kt], pl[2 * kt + 1], ph[2 * kt + 1]};
            int kcol = kb * 64 + kt * 16 + (lane >> 4) * 8;
            #pragma unroll
            for (int dn2 = 0; dn2 < 2; dn2++) {
                int drow = dn2 * 16 + (lane & 15);
                unsigned t[4];
                ldmx4(t, smem_u32(vt + drow * VSTR + kcol));
                mma_bf16(o[2 * dn2], a, t[0], t[2]);
                mma_bf16(o[2 * dn2 + 1], a, t[1], t[3]);
            }
        }
    }

    sum_lo += __shfl_xor_sync(0xFFFFFFFFu, sum_lo, 1);
    sum_lo += __shfl_xor_sync(0xFFFFFFFFu, sum_lo, 2);
    sum_hi += __shfl_xor_sync(0xFFFFFFFFu, sum_hi, 1);
    sum_hi += __shfl_xor_sync(0xFFFFFFFFu, sum_hi, 2);
    float inv_lo = 1.f / sum_lo;
    float inv_hi = 1.f / sum_hi;
    int r = lane >> 2, cc = (lane & 3) * 2;
    int q0 = qt * 128 + m0 + r;
    #pragma unroll
    for (int dn = 0; dn < 4; dn++) {
        int d = dn * 8 + cc;
        float2 t0 = make_float2(o[dn][0] * inv_lo, o[dn][1] * inv_lo);
        float2 t1 = make_float2(o[dn][2] * inv_hi, o[dn][3] * inv_hi);
        *(float2*)(out + ((size_t)(b * NPIX + q0)) * C + head * HD + d) = t0;
        *(float2*)(out + ((size_t)(b * NPIX + q0 + 8)) * C + head * HD + d) = t1;
    }
}

// ---------------- launch ------------------------------------------------------
extern "C" void kernel_launch(void* const* d_in, const int* in_sizes, int n_in,
                              void* d_out, int out_size) {
    int base = (n_in >= 19) ? 3 : 1;
    const float* x      = (const float*)d_in[0];
    const float* Wq     = (const float*)d_in[base + 0];
    const float* bq     = (const float*)d_in[base + 1];
    const float* Wkv    = (const float*)d_in[base + 2];
    const float* bkv    = (const float*)d_in[base + 3];
    const float* sr_w1  = (const float*)d_in[base + 4];
    const float* bn1g   = (const float*)d_in[base + 5];
    const float* bn1b   = (const float*)d_in[base + 6];
    const float* bn1m   = (const float*)d_in[base + 7];
    const float* bn1v   = (const float*)d_in[base + 8];
    const float* sr_w2  = (const float*)d_in[base + 9];
    const float* bn2g   = (const float*)d_in[base + 10];
    const float* bn2b   = (const float*)d_in[base + 11];
    const float* bn2m   = (const float*)d_in[base + 12];
    const float* bn2v   = (const float*)d_in[base + 13];
    const float* lw     = (const float*)d_in[base + 14];
    const float* lb     = (const float*)d_in[base + 15];
    float* out = (float*)d_out;

    float* gq = nullptr;  cudaGetSymbolAddress((void**)&gq, g_q);
    float* gkp = nullptr; cudaGetSymbolAddress((void**)&gkp, g_kvp);
    __nv_bfloat16 *xh, *xl, *wqh, *wql, *wkvh, *wkvl, *kv2h, *kv2l;
    cudaGetSymbolAddress((void**)&xh, g_xh);
    cudaGetSymbolAddress((void**)&xl, g_xl);
    cudaGetSymbolAddress((void**)&wqh, g_wqh);
    cudaGetSymbolAddress((void**)&wql, g_wql);
    cudaGetSymbolAddress((void**)&wkvh, g_wkvh);
    cudaGetSymbolAddress((void**)&wkvl, g_wkvl);
    cudaGetSymbolAddress((void**)&kv2h, g_kv2h);
    cudaGetSymbolAddress((void**)&kv2l, g_kv2l);

    const int smem128 = 2 * (2 * 128 * GSTR + 2 * 128 * GSTR) * 2;  // 81920
    const int smem64  = 2 * (2 * 64 * GSTR + 2 * 128 * GSTR) * 2;   // 61440
    cudaFuncSetAttribute(gemm_mma_kernel<128>,
                         cudaFuncAttributeMaxDynamicSharedMemorySize, smem128);
    cudaFuncSetAttribute(gemm_mma_kernel<64>,
                         cudaFuncAttributeMaxDynamicSharedMemorySize, smem64);
    cudaFuncSetAttribute(attn_kernel,
                         cudaFuncAttributeMaxDynamicSharedMemorySize, ATTN_SMEM);

    // pre-split to bf16 hi/lo + weight transposes
    int nx4 = BATCH * NPIX * C / 4;
    split_kernel<<<(nx4 + 255) / 256, 256>>>(x, xh, xl, nx4);
    split_kernel<<<(C * C / 4 + 255) / 256, 256>>>(Wq, wqh, wql, C * C / 4);
    split_kernel<<<(2 * C * C / 4 + 255) / 256, 256>>>(Wkv, wkvh, wkvl,
                                                        2 * C * C / 4);
    wtr_kernel<<<49, 256>>>(sr_w1, lw);

    gemm_mma_kernel<128><<<dim3(BATCH * NPIX / 128, C / 128), 256, smem128>>>(
        xh, xl, wqh, wql, bq, gq, C);
    srconv_kernel<<<dim3(MRED, BATCH), 256>>>(x, bn1g, bn1b, bn1m, bn1v,
                                              sr_w2, bn2g, bn2b, bn2m, bn2v);
    localconv_kernel<<<dim3(MRED, BATCH), 128>>>(lb);
    gemm_mma_kernel<64><<<dim3(BATCH * MRED / 64, 2 * C / 128), 256, smem64>>>(
        kv2h, kv2l, wkvh, wkvl, bkv, gkp, 2 * C);
    attn_kernel<<<dim3(NPIX / 128, HEADS, BATCH), 256, ATTN_SMEM>>>(out);
}

// round 10
// speedup vs baseline: 3.5655x; 1.0411x over previous
#include <cuda_runtime.h>
#include <cuda_bf16.h>
#include <math.h>
#include <string.h>

#define BATCH 8
#define C 256
#define NPIX 4096
#define HIMG 64
#define WIMG 64
#define MRED 256
#define HEADS 8
#define HD 32
#define ATTN_SCALE 0.17677669529663687f
#define EPS 1e-5f

// ---------------- scratch ----------------------------------------------------
__device__ float g_kvred[BATCH * MRED * C];   // (b, m, c)
// pre-split bf16 operands
__device__ __nv_bfloat16 g_xh[BATCH * NPIX * C], g_xl[BATCH * NPIX * C];
__device__ __nv_bfloat16 g_wqh[C * C], g_wql[C * C];
__device__ __nv_bfloat16 g_wkvh[2 * C * C], g_wkvl[2 * C * C];
__device__ __nv_bfloat16 g_kv2h[BATCH * MRED * C], g_kv2l[BATCH * MRED * C];
// q projection, pre-scaled hi/lo bf16 (b*n, c)
__device__ __nv_bfloat16 g_qh[BATCH * NPIX * C], g_ql[BATCH * NPIX * C];
// kv projection: K hi/lo split + V bf16, all (b, m, c)
__device__ __nv_bfloat16 g_kh[BATCH * MRED * C], g_kl[BATCH * MRED * C];
__device__ __nv_bfloat16 g_v[BATCH * MRED * C];
// transposed conv weights [k][c]
__device__ float g_w7t[49 * C];
__device__ float g_lwt[9 * C];

// ---------------- helpers ------------------------------------------------------
__device__ __forceinline__ unsigned smem_u32(const void* p) {
    unsigned a;
    asm("{ .reg .u64 t; cvta.to.shared.u64 t, %1; cvt.u32.u64 %0, t; }"
        : "=r"(a) : "l"(p));
    return a;
}
__device__ __forceinline__ void cp16(unsigned dst, const void* src) {
    asm volatile("cp.async.ca.shared.global [%0], [%1], 16;"
                 :: "r"(dst), "l"(src));
}
#define CP_COMMIT() asm volatile("cp.async.commit_group;" ::: "memory")
#define CP_WAIT(n)  asm volatile("cp.async.wait_group %0;" :: "n"(n) : "memory")

__device__ __forceinline__ void ldmx4(unsigned* r, unsigned addr) {
    asm volatile("ldmatrix.sync.aligned.m8n8.x4.shared.b16 {%0,%1,%2,%3}, [%4];"
                 : "=r"(r[0]), "=r"(r[1]), "=r"(r[2]), "=r"(r[3]) : "r"(addr));
}
__device__ __forceinline__ void mma_bf16(float* c, const unsigned* a,
                                         unsigned b0, unsigned b1) {
    asm volatile(
        "mma.sync.aligned.m16n8k16.row.col.f32.bf16.bf16.f32 "
        "{%0,%1,%2,%3}, {%4,%5,%6,%7}, {%8,%9}, {%0,%1,%2,%3};"
        : "+f"(c[0]), "+f"(c[1]), "+f"(c[2]), "+f"(c[3])
        : "r"(a[0]), "r"(a[1]), "r"(a[2]), "r"(a[3]), "r"(b0), "r"(b1));
}
__device__ __forceinline__ unsigned pack_bf16x2(float lo, float hi) {
    unsigned d;
    asm("cvt.rn.bf16x2.f32 %0, %1, %2;" : "=r"(d) : "f"(hi), "f"(lo));
    return d;
}
__device__ __forceinline__ void split_store(__nv_bfloat16* hi, __nv_bfloat16* lo,
                                            size_t idx, float a0, float a1) {
    __nv_bfloat16 h0 = __float2bfloat16(a0);
    __nv_bfloat16 h1 = __float2bfloat16(a1);
    *(__nv_bfloat162*)(hi + idx) = __nv_bfloat162(h0, h1);
    *(__nv_bfloat162*)(lo + idx) = __nv_bfloat162(
        __float2bfloat16(a0 - __bfloat162float(h0)),
        __float2bfloat16(a1 - __bfloat162float(h1)));
}

// ---------------- fp32 -> bf16 hi/lo split (x) --------------------------------
__global__ __launch_bounds__(256) void split_kernel(
    const float* __restrict__ src, __nv_bfloat16* __restrict__ hi,
    __nv_bfloat16* __restrict__ lo, int n4) {
    int i = blockIdx.x * 256 + threadIdx.x;
    if (i >= n4) return;
    float4 v = ((const float4*)src)[i];
    split_store(hi, lo, 4 * (size_t)i, v.x, v.y);
    split_store(hi, lo, 4 * (size_t)i + 2, v.z, v.w);
}

// ---------------- weights prep: Wq/Wkv split + conv-weight transpose ----------
__global__ __launch_bounds__(256) void prep_weights_kernel(
    const float* __restrict__ Wq, const float* __restrict__ Wkv,
    const float* __restrict__ w7, const float* __restrict__ lw) {
    int bx = blockIdx.x, tid = threadIdx.x;
    if (bx < 64) {                       // Wq: 16384 float4
        int i = bx * 256 + tid;
        float4 v = ((const float4*)Wq)[i];
        split_store(g_wqh, g_wql, 4 * (size_t)i, v.x, v.y);
        split_store(g_wqh, g_wql, 4 * (size_t)i + 2, v.z, v.w);
    } else if (bx < 192) {               // Wkv: 32768 float4
        int i = (bx - 64) * 256 + tid;
        float4 v = ((const float4*)Wkv)[i];
        split_store(g_wkvh, g_wkvl, 4 * (size_t)i, v.x, v.y);
        split_store(g_wkvh, g_wkvl, 4 * (size_t)i + 2, v.z, v.w);
    } else {                             // conv weight transpose, k = bx-192
        int k = bx - 192;
        g_w7t[k * C + tid] = w7[tid * 49 + k];
        if (k < 9) g_lwt[k * C + tid] = lw[tid * 9 + k];
    }
}

// ---------------- HMMA GEMM, bf16-split inputs + cp.async double buffer -------
// EPI 0: q-style (scale then hi/lo split out). EPI 1: kv-style (K split, V bf16).
#define GSTR 40
template <int BM, int EPI>
__global__ __launch_bounds__(256, 2) void gemm_mma_kernel(
    const __nv_bfloat16* __restrict__ Xh, const __nv_bfloat16* __restrict__ Xl,
    const __nv_bfloat16* __restrict__ Wh, const __nv_bfloat16* __restrict__ Wl,
    const float* __restrict__ bias,
    __nv_bfloat16* __restrict__ Oh, __nv_bfloat16* __restrict__ Ol,
    __nv_bfloat16* __restrict__ Ov, float scale) {
    constexpr int MT = BM / 64;
    constexpr int SX = BM * GSTR;
    constexpr int SW = 128 * GSTR;
    constexpr int STG = 2 * SX + 2 * SW;
    extern __shared__ __nv_bfloat16 gsm[];

    int tid = threadIdx.x, lane = tid & 31, w = tid >> 5;
    int bm = blockIdx.x * BM, bn = blockIdx.y * 128;
    int wm = (w & 3) * (16 * MT), wn = (w >> 2) * 64;
    int lr = tid >> 2, lch = (tid & 3) * 8;

    float acc[MT][8][4];
    #pragma unroll
    for (int mt = 0; mt < MT; mt++)
        #pragma unroll
        for (int nt = 0; nt < 8; nt++)
            #pragma unroll
            for (int q = 0; q < 4; q++) acc[mt][nt][q] = 0.f;

    #define XH(s) (gsm + (s) * STG)
    #define XL(s) (gsm + (s) * STG + SX)
    #define WH(s) (gsm + (s) * STG + 2 * SX)
    #define WL(s) (gsm + (s) * STG + 2 * SX + SW)

    #define LOAD_STAGE(s, kc) do {                                            \
        _Pragma("unroll")                                                      \
        for (int rr = 0; rr < MT; rr++) {                                      \
            cp16(smem_u32(XH(s) + (lr + 64 * rr) * GSTR + lch),                \
                 Xh + (size_t)(bm + lr + 64 * rr) * C + (kc) + lch);           \
            cp16(smem_u32(XL(s) + (lr + 64 * rr) * GSTR + lch),                \
                 Xl + (size_t)(bm + lr + 64 * rr) * C + (kc) + lch);           \
        }                                                                      \
        _Pragma("unroll")                                                      \
        for (int rr = 0; rr < 2; rr++) {                                       \
            cp16(smem_u32(WH(s) + (lr + 64 * rr) * GSTR + lch),                \
                 Wh + (size_t)(bn + lr + 64 * rr) * C + (kc) + lch);           \
            cp16(smem_u32(WL(s) + (lr + 64 * rr) * GSTR + lch),                \
                 Wl + (size_t)(bn + lr + 64 * rr) * C + (kc) + lch);           \
        }                                                                      \
    } while (0)

    LOAD_STAGE(0, 0);
    CP_COMMIT();

    #pragma unroll
    for (int kk = 0; kk < 8; kk++) {
        int s = kk & 1;
        if (kk < 7) {
            LOAD_STAGE(s ^ 1, (kk + 1) * 32);
            CP_COMMIT();
            CP_WAIT(1);
        } else {
            CP_WAIT(0);
        }
        __syncthreads();

        #pragma unroll
        for (int ks = 0; ks < 2; ks++) {
            int acol = ks * 16 + (lane >> 4) * 8;
            int arow = wm + (lane & 15);
            unsigned ah[MT][4], al[MT][4];
            #pragma unroll
            for (int mt = 0; mt < MT; mt++) {
                ldmx4(ah[mt], smem_u32(XH(s) + (arow + mt * 16) * GSTR + acol));
                ldmx4(al[mt], smem_u32(XL(s) + (arow + mt * 16) * GSTR + acol));
            }
            unsigned bh[8][2], bl[8][2];
            #pragma unroll
            for (int nt4 = 0; nt4 < 4; nt4++) {
                int brow = wn + nt4 * 16 + (lane & 15);
                unsigned t[4];
                ldmx4(t, smem_u32(WH(s) + brow * GSTR + acol));
                bh[nt4 * 2][0] = t[0]; bh[nt4 * 2][1] = t[2];
                bh[nt4 * 2 + 1][0] = t[1]; bh[nt4 * 2 + 1][1] = t[3];
                ldmx4(t, smem_u32(WL(s) + brow * GSTR + acol));
                bl[nt4 * 2][0] = t[0]; bl[nt4 * 2][1] = t[2];
                bl[nt4 * 2 + 1][0] = t[1]; bl[nt4 * 2 + 1][1] = t[3];
            }
            #pragma unroll
            for (int mt = 0; mt < MT; mt++)
                #pragma unroll
                for (int nt = 0; nt < 8; nt++) {
                    mma_bf16(acc[mt][nt], ah[mt], bh[nt][0], bh[nt][1]);
                    mma_bf16(acc[mt][nt], ah[mt], bl[nt][0], bl[nt][1]);
                    mma_bf16(acc[mt][nt], al[mt], bh[nt][0], bh[nt][1]);
                }
        }
        __syncthreads();
    }

    int r_in = (lane >> 2), c_in = (lane & 3) * 2;
    #pragma unroll
    for (int mt = 0; mt < MT; mt++)
        #pragma unroll
        for (int nt = 0; nt < 8; nt++) {
            int col = bn + wn + nt * 8 + c_in;
            float b0 = bias[col], b1 = bias[col + 1];
            int row0 = bm + wm + mt * 16 + r_in;
            float s00 = (acc[mt][nt][0] + b0) * scale;
            float s01 = (acc[mt][nt][1] + b1) * scale;
            float s10 = (acc[mt][nt][2] + b0) * scale;
            float s11 = (acc[mt][nt][3] + b1) * scale;
            if (EPI == 0 || col < C) {
                size_t i0 = (size_t)row0 * C + col;
                split_store(Oh, Ol, i0, s00, s01);
                split_store(Oh, Ol, i0 + 8 * C, s10, s11);
            } else {
                size_t i0 = (size_t)row0 * C + (col - C);
                *(__nv_bfloat162*)(Ov + i0) =
                    __nv_bfloat162(__float2bfloat16(s00), __float2bfloat16(s01));
                *(__nv_bfloat162*)(Ov + i0 + 8 * C) =
                    __nv_bfloat162(__float2bfloat16(s10), __float2bfloat16(s11));
            }
        }
    #undef LOAD_STAGE
    #undef XH
    #undef XL
    #undef WH
    #undef WL
}

// ---------------- SR conv (transposed weights) --------------------------------
__global__ __launch_bounds__(256) void srconv_kernel(
    const float* __restrict__ x,
    const float* __restrict__ g1, const float* __restrict__ b1,
    const float* __restrict__ m1, const float* __restrict__ v1,
    const float* __restrict__ w2,
    const float* __restrict__ g2, const float* __restrict__ b2,
    const float* __restrict__ m2, const float* __restrict__ v2) {
    int opix = blockIdx.x;
    int b = blockIdx.y;
    int c = threadIdx.x;
    int oy = opix >> 4, ox = opix & 15;
    const float* xb = x + (size_t)b * NPIX * C;
    float s = 0.f;
    #pragma unroll
    for (int ky = 0; ky < 7; ky++) {
        int iy = oy * 4 - 3 + ky;
        if (iy < 0 || iy >= HIMG) continue;
        #pragma unroll
        for (int kx = 0; kx < 7; kx++) {
            int ix = ox * 4 - 3 + kx;
            if (ix < 0 || ix >= WIMG) continue;
            s += xb[(size_t)(iy * WIMG + ix) * C + c] * g_w7t[(ky * 7 + kx) * C + c];
        }
    }
    float sc1 = g1[c] * rsqrtf(v1[c] + EPS);
    float val = s * sc1 + (b1[c] - m1[c] * sc1);
    val = 0.5f * val * (1.f + erff(val * 0.7071067811865476f));
    val *= w2[c];
    float sc2 = g2[c] * rsqrtf(v2[c] + EPS);
    val = val * sc2 + (b2[c] - m2[c] * sc2);
    g_kvred[((size_t)b * MRED + opix) * C + c] = val;
}

// ---------------- local 3x3 dwconv + residual -> bf16 hi/lo -------------------
__global__ __launch_bounds__(128) void localconv_kernel(
    const float* __restrict__ lb) {
    int opix = blockIdx.x;
    int b = blockIdx.y;
    int c = threadIdx.x * 2;
    int y = opix >> 4, xq = opix & 15;
    const float* src = g_kvred + (size_t)b * MRED * C;
    float2 ctr = *(const float2*)(src + (size_t)opix * C + c);
    float s0 = lb[c] + ctr.x;
    float s1 = lb[c + 1] + ctr.y;
    #pragma unroll
    for (int dy = -1; dy <= 1; dy++) {
        int yy = y + dy;
        if (yy < 0 || yy >= 16) continue;
        #pragma unroll
        for (int dx = -1; dx <= 1; dx++) {
            int xx = xq + dx;
            if (xx < 0 || xx >= 16) continue;
            float2 wv = *(const float2*)(g_lwt + ((dy + 1) * 3 + (dx + 1)) * C + c);
            float2 sv = *(const float2*)(src + (size_t)(yy * 16 + xx) * C + c);
            s0 += sv.x * wv.x;
            s1 += sv.y * wv.y;
        }
    }
    split_store(g_kv2h, g_kv2l, ((size_t)b * MRED + opix) * C + c, s0, s1);
}

// ---------------- flash attention via mma.sync bf16 ---------------------------
// smem: K hi/lo [256][QSTR] + Vt [32][VSTR]; Q fragments loaded from gmem.
#define QSTR 40
#define VSTR 264
#define SM_KHI 0
#define SM_KLO (SM_KHI + 256 * QSTR)
#define SM_VT  (SM_KLO + 256 * QSTR)
#define ATTN_SMEM ((SM_VT + 32 * VSTR) * 2)

__global__ __launch_bounds__(256, 2) void attn_kernel(float* __restrict__ out) {
    extern __shared__ __nv_bfloat16 sm[];
    __nv_bfloat16* khi = sm + SM_KHI;
    __nv_bfloat16* klo = sm + SM_KLO;
    __nv_bfloat16* vt  = sm + SM_VT;

    int tid = threadIdx.x, lane = tid & 31, w = tid >> 5;
    int qt = blockIdx.x, head = blockIdx.y, b = blockIdx.z;

    // ---- stage K (hi/lo bf16 direct copy) and V transposed ----
    for (int i = tid; i < 1024; i += 256) {
        int m = i >> 2, ch = (i & 3) * 8;
        size_t src = (size_t)(b * MRED + m) * C + head * HD + ch;
        *(uint4*)(khi + m * QSTR + ch) = *(const uint4*)(g_kh + src);
        *(uint4*)(klo + m * QSTR + ch) = *(const uint4*)(g_kl + src);
    }
    for (int i = tid; i < 256 * 16; i += 256) {
        int m = i >> 4, d2 = (i & 15) * 2;
        __nv_bfloat162 v = *(const __nv_bfloat162*)(
            g_v + (size_t)(b * MRED + m) * C + head * HD + d2);
        vt[d2 * VSTR + m] = v.x;
        vt[(d2 + 1) * VSTR + m] = v.y;
    }

    // ---- load Q fragments directly from gmem (pre-scaled hi/lo) ----
    int m0 = w * 16;
    unsigned qh[2][4], ql[2][4];
    {
        size_t qbase = (size_t)(b * NPIX + qt * 128 + m0 + (lane >> 2)) * C
                       + head * HD + (lane & 3) * 2;
        #pragma unroll
        for (int kt = 0; kt < 2; kt++) {
            size_t o0 = qbase + kt * 16;
            qh[kt][0] = *(const unsigned*)(g_qh + o0);
            qh[kt][1] = *(const unsigned*)(g_qh + o0 + 8 * C);
            qh[kt][2] = *(const unsigned*)(g_qh + o0 + 8);
            qh[kt][3] = *(const unsigned*)(g_qh + o0 + 8 * C + 8);
            ql[kt][0] = *(const unsigned*)(g_ql + o0);
            ql[kt][1] = *(const unsigned*)(g_ql + o0 + 8 * C);
            ql[kt][2] = *(const unsigned*)(g_ql + o0 + 8);
            ql[kt][3] = *(const unsigned*)(g_ql + o0 + 8 * C + 8);
        }
    }
    __syncthreads();

    float m_lo = -1e30f, m_hi = -1e30f, sum_lo = 0.f, sum_hi = 0.f;
    float o[4][4];
    #pragma unroll
    for (int i = 0; i < 4; i++)
        #pragma unroll
        for (int j = 0; j < 4; j++) o[i][j] = 0.f;

    #pragma unroll
    for (int kb = 0; kb < 4; kb++) {
        float s[8][4];
        #pragma unroll
        for (int j = 0; j < 8; j++)
            #pragma unroll
            for (int q = 0; q < 4; q++) s[j][q] = 0.f;
        #pragma unroll
        for (int kt = 0; kt < 2; kt++) {
            int col = kt * 16 + (lane >> 4) * 8;
            #pragma unroll
            for (int jj = 0; jj < 4; jj++) {
                int row = kb * 64 + jj * 16 + (lane & 15);
                unsigned th[4], tl[4];
                ldmx4(th, smem_u32(khi + row * QSTR + col));
                ldmx4(tl, smem_u32(klo + row * QSTR + col));
                mma_bf16(s[2 * jj], qh[kt], th[0], th[2]);
                mma_bf16(s[2 * jj], qh[kt], tl[0], tl[2]);
                mma_bf16(s[2 * jj], ql[kt], th[0], th[2]);
                mma_bf16(s[2 * jj + 1], qh[kt], th[1], th[3]);
                mma_bf16(s[2 * jj + 1], qh[kt], tl[1], tl[3]);
                mma_bf16(s[2 * jj + 1], ql[kt], th[1], th[3]);
            }
        }
        float bm_lo = -1e30f, bm_hi = -1e30f;
        #pragma unroll
        for (int j = 0; j < 8; j++) {
            bm_lo = fmaxf(bm_lo, fmaxf(s[j][0], s[j][1]));
            bm_hi = fmaxf(bm_hi, fmaxf(s[j][2], s[j][3]));
        }
        bm_lo = fmaxf(bm_lo, __shfl_xor_sync(0xFFFFFFFFu, bm_lo, 1));
        bm_lo = fmaxf(bm_lo, __shfl_xor_sync(0xFFFFFFFFu, bm_lo, 2));
        bm_hi = fmaxf(bm_hi, __shfl_xor_sync(0xFFFFFFFFu, bm_hi, 1));
        bm_hi = fmaxf(bm_hi, __shfl_xor_sync(0xFFFFFFFFu, bm_hi, 2));
        float nm_lo = fmaxf(m_lo, bm_lo);
        float nm_hi = fmaxf(m_hi, bm_hi);
        float corr_lo = exp2f(m_lo - nm_lo);
        float corr_hi = exp2f(m_hi - nm_hi);
        m_lo = nm_lo; m_hi = nm_hi;
        sum_lo *= corr_lo; sum_hi *= corr_hi;
        #pragma unroll
        for (int dn = 0; dn < 4; dn++) {
            o[dn][0] *= corr_lo; o[dn][1] *= corr_lo;
            o[dn][2] *= corr_hi; o[dn][3] *= corr_hi;
        }
        unsigned pl[8], ph[8];
        #pragma unroll
        for (int j = 0; j < 8; j++) {
            float p0 = exp2f(s[j][0] - m_lo);
            float p1 = exp2f(s[j][1] - m_lo);
            float p2 = exp2f(s[j][2] - m_hi);
            float p3 = exp2f(s[j][3] - m_hi);
            sum_lo += p0 + p1;
            sum_hi += p2 + p3;
            pl[j] = pack_bf16x2(p0, p1);
            ph[j] = pack_bf16x2(p2, p3);
        }
        #pragma unroll
        for (int kt = 0; kt < 4; kt++) {
            unsigned a[4] = {pl[2 * kt], ph[2 * kt], pl[2 * kt + 1], ph[2 * kt + 1]};
            int kcol = kb * 64 + kt * 16 + (lane >> 4) * 8;
            #pragma unroll
            for (int dn2 = 0; dn2 < 2; dn2++) {
                int drow = dn2 * 16 + (lane & 15);
                unsigned t[4];
                ldmx4(t, smem_u32(vt + drow * VSTR + kcol));
                mma_bf16(o[2 * dn2], a, t[0], t[2]);
                mma_bf16(o[2 * dn2 + 1], a, t[1], t[3]);
            }
        }
    }

    sum_lo += __shfl_xor_sync(0xFFFFFFFFu, sum_lo, 1);
    sum_lo += __shfl_xor_sync(0xFFFFFFFFu, sum_lo, 2);
    sum_hi += __shfl_xor_sync(0xFFFFFFFFu, sum_hi, 1);
    sum_hi += __shfl_xor_sync(0xFFFFFFFFu, sum_hi, 2);
    float inv_lo = 1.f / sum_lo;
    float inv_hi = 1.f / sum_hi;
    int r = lane >> 2, cc = (lane & 3) * 2;
    int q0 = qt * 128 + m0 + r;
    #pragma unroll
    for (int dn = 0; dn < 4; dn++) {
        int d = dn * 8 + cc;
        float2 t0 = make_float2(o[dn][0] * inv_lo, o[dn][1] * inv_lo);
        float2 t1 = make_float2(o[dn][2] * inv_hi, o[dn][3] * inv_hi);
        *(float2*)(out + ((size_t)(b * NPIX + q0)) * C + head * HD + d) = t0;
        *(float2*)(out + ((size_t)(b * NPIX + q0 + 8)) * C + head * HD + d) = t1;
    }
}

// ---------------- launch ------------------------------------------------------
extern "C" void kernel_launch(void* const* d_in, const int* in_sizes, int n_in,
                              void* d_out, int out_size) {
    int base = (n_in >= 19) ? 3 : 1;
    const float* x      = (const float*)d_in[0];
    const float* Wq     = (const float*)d_in[base + 0];
    const float* bq     = (const float*)d_in[base + 1];
    const float* Wkv    = (const float*)d_in[base + 2];
    const float* bkv    = (const float*)d_in[base + 3];
    const float* sr_w1  = (const float*)d_in[base + 4];
    const float* bn1g   = (const float*)d_in[base + 5];
    const float* bn1b   = (const float*)d_in[base + 6];
    const float* bn1m   = (const float*)d_in[base + 7];
    const float* bn1v   = (const float*)d_in[base + 8];
    const float* sr_w2  = (const float*)d_in[base + 9];
    const float* bn2g   = (const float*)d_in[base + 10];
    const float* bn2b   = (const float*)d_in[base + 11];
    const float* bn2m   = (const float*)d_in[base + 12];
    const float* bn2v   = (const float*)d_in[base + 13];
    const float* lw     = (const float*)d_in[base + 14];
    const float* lb     = (const float*)d_in[base + 15];
    float* out = (float*)d_out;

    __nv_bfloat16 *xh, *xl, *wqh, *wql, *wkvh, *wkvl, *kv2h, *kv2l;
    __nv_bfloat16 *qh, *ql, *kh, *kl, *vv;
    cudaGetSymbolAddress((void**)&xh, g_xh);
    cudaGetSymbolAddress((void**)&xl, g_xl);
    cudaGetSymbolAddress((void**)&wqh, g_wqh);
    cudaGetSymbolAddress((void**)&wql, g_wql);
    cudaGetSymbolAddress((void**)&wkvh, g_wkvh);
    cudaGetSymbolAddress((void**)&wkvl, g_wkvl);
    cudaGetSymbolAddress((void**)&kv2h, g_kv2h);
    cudaGetSymbolAddress((void**)&kv2l, g_kv2l);
    cudaGetSymbolAddress((void**)&qh, g_qh);
    cudaGetSymbolAddress((void**)&ql, g_ql);
    cudaGetSymbolAddress((void**)&kh, g_kh);
    cudaGetSymbolAddress((void**)&kl, g_kl);
    cudaGetSymbolAddress((void**)&vv, g_v);

    const int smem128 = 2 * (2 * 128 * GSTR + 2 * 128 * GSTR) * 2;  // 81920
    const int smem64  = 2 * (2 * 64 * GSTR + 2 * 128 * GSTR) * 2;   // 61440
    cudaFuncSetAttribute((const void*)gemm_mma_kernel<128, 0>,
                         cudaFuncAttributeMaxDynamicSharedMemorySize, smem128);
    cudaFuncSetAttribute((const void*)gemm_mma_kernel<64, 1>,
                         cudaFuncAttributeMaxDynamicSharedMemorySize, smem64);
    cudaFuncSetAttribute((const void*)attn_kernel,
                         cudaFuncAttributeMaxDynamicSharedMemorySize, ATTN_SMEM);

    const float QSC = ATTN_SCALE * 1.4426950408889634f;

    int nx4 = BATCH * NPIX * C / 4;
    split_kernel<<<(nx4 + 255) / 256, 256>>>(x, xh, xl, nx4);
    prep_weights_kernel<<<192 + 49, 256>>>(Wq, Wkv, sr_w1, lw);

    gemm_mma_kernel<128, 0><<<dim3(BATCH * NPIX / 128, C / 128), 256, smem128>>>(
        xh, xl, wqh, wql, bq, qh, ql, nullptr, QSC);
    srconv_kernel<<<dim3(MRED, BATCH), 256>>>(x, bn1g, bn1b, bn1m, bn1v,
                                              sr_w2, bn2g, bn2b, bn2m, bn2v);
    localconv_kernel<<<dim3(MRED, BATCH), 128>>>(lb);
    gemm_mma_kernel<64, 1><<<dim3(BATCH * MRED / 64, 2 * C / 128), 256, smem64>>>(
        kv2h, kv2l, wkvh, wkvl, bkv, kh, kl, vv, 1.0f);
    attn_kernel<<<dim3(NPIX / 128, HEADS, BATCH), 256, ATTN_SMEM>>>(out);
}